// round 14
// baseline (speedup 1.0000x reference)
#include <cuda_runtime.h>
#include <cuda_bf16.h>
#include <math.h>
#include <stdint.h>

#define Bv 8
#define Cv 256
#define HWv 4096
#define NHv 4
#define HDv 64

typedef __nv_bfloat16 bf16;

// ---------------- scratch (device globals; no allocations) ----------------
__device__ bf16 g_xa_h [Bv*HWv*Cv];
__device__ bf16 g_xa_l [Bv*HWv*Cv];
__device__ bf16 g_xkv_h[2*Bv*HWv*Cv];
__device__ bf16 g_xkv_l[2*Bv*HWv*Cv];
__device__ bf16 g_xqkv_h[Bv*HWv*Cv];
__device__ bf16 g_xqkv_l[Bv*HWv*Cv];
__device__ bf16 g_xh_h [Bv*HWv*Cv];
__device__ bf16 g_xh_l [Bv*HWv*Cv];
__device__ bf16 g_w_h[393216];
__device__ bf16 g_w_l[393216];
__device__ bf16 g_qb_h[Bv*Cv*HWv];         // q K-major [b][c][hw]
__device__ bf16 g_qb_l[Bv*Cv*HWv];
__device__ bf16 g_kb_h[2*Bv*Cv*HWv];       // k K-major [sb][c][hw]
__device__ bf16 g_kb_l[2*Bv*Cv*HWv];
__device__ bf16 g_vt_h[2*Bv*HWv*Cv];       // v transposed [sb][hw][c]
__device__ bf16 g_vt_l[2*Bv*HWv*Cv];
__device__ bf16 g_ph[2*Bv*NHv*HDv*HDv];
__device__ bf16 g_pl[2*Bv*NHv*HDv*HDv];
__device__ float g_x  [Bv*Cv*HWv];
__device__ float g_qinv[Bv*Cv];            // raw squared-sum accum
__device__ float g_kinv[2*Bv*Cv];
__device__ float g_lnsum[Bv*HWv];          // mlp-LN fused stats
__device__ float g_lnsq [Bv*HWv];
__device__ float g_spart[8*2*Bv*NHv*HDv*HDv];   // 8 splits

// ---------------- helpers ----------------
__device__ __forceinline__ uint32_t smem_to_u32(const void* p){
    uint32_t a;
    asm("{ .reg .u64 t; cvta.to.shared.u64 t, %1; cvt.u32.u64 %0, t; }" : "=r"(a) : "l"(p));
    return a;
}
__device__ __forceinline__ void ldmatrix_x4(uint32_t* r, uint32_t addr){
    asm volatile("ldmatrix.sync.aligned.m8n8.x4.shared.b16 {%0,%1,%2,%3}, [%4];"
        : "=r"(r[0]), "=r"(r[1]), "=r"(r[2]), "=r"(r[3]) : "r"(addr));
}
__device__ __forceinline__ void mma_bf16(float* d, const uint32_t* a, uint32_t b0, uint32_t b1){
    asm volatile("mma.sync.aligned.m16n8k16.row.col.f32.bf16.bf16.f32 "
        "{%0,%1,%2,%3}, {%4,%5,%6,%7}, {%8,%9}, {%0,%1,%2,%3};"
        : "+f"(d[0]), "+f"(d[1]), "+f"(d[2]), "+f"(d[3])
        : "r"(a[0]), "r"(a[1]), "r"(a[2]), "r"(a[3]), "r"(b0), "r"(b1));
}
__device__ __forceinline__ float gelu_f(float v){
    float c = v + 0.044715f*v*v*v;
    float t = tanhf(0.7978845608028654f * c);
    return 0.5f*v*(1.f+t);
}
__device__ __forceinline__ void split_bf16(float v, bf16& h, bf16& l){
    h = __float2bfloat16(v);
    l = __float2bfloat16(v - __bfloat162float(h));
}

// ---------------- all-5 weight conversions in one launch ----------------
__global__ void wconv5_kernel(const float* __restrict__ w0, const float* __restrict__ w1,
                              const float* __restrict__ w2, const float* __restrict__ w3,
                              const float* __restrict__ w4,
                              bf16* __restrict__ h, bf16* __restrict__ l){
    int i = blockIdx.x*256 + threadIdx.x;          // 0..393215
    const float* src; int j;
    if (i < 65536)       { src = w0; j = i; }
    else if (i < 196608) { src = w1; j = i - 65536; }
    else if (i < 262144) { src = w2; j = i - 196608; }
    else if (i < 327680) { src = w3; j = i - 262144; }
    else                 { src = w4; j = i - 327680; }
    bf16 hh, ll; split_bf16(src[j], hh, ll);
    h[i] = hh; l[i] = ll;
}

// ---------------- merged LayerNorm (3 input tensors) -> XT bf16 hi/lo ------------
__global__ __launch_bounds__(256) void ln3_kernel(
        const float* __restrict__ img, const float* __restrict__ aux0,
        const float* __restrict__ aux1,
        const float* __restrict__ qw, const float* __restrict__ qb,
        const float* __restrict__ kw, const float* __restrict__ kb,
        bf16* __restrict__ xa_h, bf16* __restrict__ xa_l,
        bf16* __restrict__ xkv_h, bf16* __restrict__ xkv_l)
{
    int which = blockIdx.y;
    const float* x = (which == 0) ? img : (which == 1) ? aux0 : aux1;
    const float* w = (which == 0) ? qw : kw;
    const float* bias = (which == 0) ? qb : kb;
    bf16* oh = (which == 0) ? xa_h : xkv_h + (size_t)(which-1)*Bv*HWv*Cv;
    bf16* ol = (which == 0) ? xa_l : xkv_l + (size_t)(which-1)*Bv*HWv*Cv;

    int idx = blockIdx.x*blockDim.x + threadIdx.x;
    int b = idx / HWv, hw = idx % HWv;
    const float* xb = x + (size_t)b*Cv*HWv + hw;
    float s = 0.f, s2 = 0.f;
    #pragma unroll 8
    for (int c = 0; c < Cv; c++){ float v = xb[(size_t)c*HWv]; s += v; s2 += v*v; }
    float m   = s * (1.f/Cv);
    float var = s2 * (1.f/Cv) - m*m;
    float inv = rsqrtf(var + 1e-5f);
    size_t base = ((size_t)b*HWv + hw) * Cv;
    for (int c8 = 0; c8 < Cv/8; c8++){
        uint4 hp, lp;
        bf16* hh = (bf16*)&hp; bf16* ll = (bf16*)&lp;
        #pragma unroll
        for (int i = 0; i < 8; i++){
            int c = c8*8 + i;
            float v = (xb[(size_t)c*HWv] - m) * inv * w[c] + bias[c];
            split_bf16(v, hh[i], ll[i]);
        }
        *(uint4*)&oh[base + c8*8] = hp;
        *(uint4*)&ol[base + c8*8] = lp;
    }
}

// ---------------- single-pass LN apply using fused stats (mlp LN) ----------------
__global__ __launch_bounds__(256) void ln_apply_kernel(const float* __restrict__ x,
        const float* __restrict__ w, const float* __restrict__ bias,
        bf16* __restrict__ oh, bf16* __restrict__ ol)
{
    int idx = blockIdx.x*blockDim.x + threadIdx.x;
    int b = idx / HWv, hw = idx % HWv;
    float s  = g_lnsum[idx];
    float s2 = g_lnsq[idx];
    float m   = s * (1.f/Cv);
    float var = s2 * (1.f/Cv) - m*m;
    float inv = rsqrtf(var + 1e-5f);
    const float* xb = x + (size_t)b*Cv*HWv + hw;
    size_t base = ((size_t)b*HWv + hw) * Cv;
    for (int c8 = 0; c8 < Cv/8; c8++){
        uint4 hp, lp;
        bf16* hh = (bf16*)&hp; bf16* ll = (bf16*)&lp;
        #pragma unroll
        for (int i = 0; i < 8; i++){
            int c = c8*8 + i;
            float v = (xb[(size_t)c*HWv] - m) * inv * w[c] + bias[c];
            split_bf16(v, hh[i], ll[i]);
        }
        *(uint4*)&oh[base + c8*8] = hp;
        *(uint4*)&ol[base + c8*8] = lp;
    }
}

// ---------------- HMMA bf16x3 GEMM (R6-proven mainloop, occ 3) -------------------
// mode 1: oxh/oxl bf16 XT [b][hw][c], +bias, gelu
// mode 2: out fp32, +bias +resid
// mode 5: mode 2 + fused LN stats atomics into g_lnsum/g_lnsq
#define RS 72
#define OFF_AH 0
#define OFF_AL 18432
#define OFF_BH 36864
#define OFF_BL 55296
#define GEMM_SMEM 73728

__global__ __launch_bounds__(256,3) void gemm_kernel(
    const bf16* __restrict__ Ah, const bf16* __restrict__ Al,
    const bf16* __restrict__ Bh, const bf16* __restrict__ Bl,
    float* __restrict__ out, bf16* __restrict__ oxh, bf16* __restrict__ oxl,
    const float* __restrict__ bias, const float* __restrict__ resid,
    int mode, int Mrows)
{
    extern __shared__ char sm[];
    uint32_t smb = smem_to_u32(sm);
    int tid = threadIdx.x, lane = tid & 31, warp = tid >> 5;
    int warp_m = warp & 3, warp_n = warp >> 2;
    int n0 = blockIdx.x*128, m0 = blockIdx.y*128, b = blockIdx.z;
    const bf16* Bhb = Bh + (size_t)b*HWv*Cv;
    const bf16* Blb = Bl + (size_t)b*HWv*Cv;

    float d[2][8][4];
    #pragma unroll
    for (int i=0;i<2;i++)
        #pragma unroll
        for (int j=0;j<8;j++)
            #pragma unroll
            for (int k=0;k<4;k++) d[i][j][k] = 0.f;

    int a_row = (lane & 7) + ((lane >> 3) & 1) * 8;
    int a_kc  = (lane >> 4) * 8;
    int b_row = (lane & 7) + (lane >> 4) * 8;
    int b_kc  = ((lane >> 3) & 1) * 8;

    for (int kt = 0; kt < 4; kt++){
        int k0 = kt*64;
        #pragma unroll
        for (int it = 0; it < 4; it++){
            int lin = tid + it*256;
            int row = lin >> 3, kk = lin & 7;
            uint32_t so = row*(RS*2) + kk*16;
            size_t ga = (size_t)(m0+row)*Cv + k0 + kk*8;
            size_t gb = (size_t)(n0+row)*Cv + k0 + kk*8;
            *(uint4*)(sm+OFF_AH+so) = *(const uint4*)(Ah +ga);
            *(uint4*)(sm+OFF_AL+so) = *(const uint4*)(Al +ga);
            *(uint4*)(sm+OFF_BH+so) = *(const uint4*)(Bhb+gb);
            *(uint4*)(sm+OFF_BL+so) = *(const uint4*)(Blb+gb);
        }
        __syncthreads();
        #pragma unroll
        for (int k16 = 0; k16 < 4; k16++){
            uint32_t ah[2][4], al[2][4];
            #pragma unroll
            for (int fm = 0; fm < 2; fm++){
                int arow = warp_m*32 + fm*16 + a_row;
                uint32_t aaddr = smb + OFF_AH + arow*(RS*2) + (k16*16 + a_kc)*2;
                ldmatrix_x4(ah[fm], aaddr);
                ldmatrix_x4(al[fm], aaddr + (OFF_AL-OFF_AH));
            }
            #pragma unroll
            for (int half = 0; half < 2; half++){
                uint32_t bh[2][4], bl[2][4];
                #pragma unroll
                for (int p = 0; p < 2; p++){
                    int nrow = warp_n*64 + half*32 + p*16 + b_row;
                    uint32_t baddr = smb + OFF_BH + nrow*(RS*2) + (k16*16 + b_kc)*2;
                    ldmatrix_x4(bh[p], baddr);
                    ldmatrix_x4(bl[p], baddr + (OFF_BL-OFF_BH));
                }
                #pragma unroll
                for (int fm = 0; fm < 2; fm++)
                    #pragma unroll
                    for (int j = 0; j < 4; j++){
                        float* dd = d[fm][half*4+j];
                        uint32_t* fh = &bh[j>>1][(j&1)*2];
                        uint32_t* fl = &bl[j>>1][(j&1)*2];
                        mma_bf16(dd, ah[fm], fh[0], fh[1]);
                        mma_bf16(dd, ah[fm], fl[0], fl[1]);
                        mma_bf16(dd, al[fm], fh[0], fh[1]);
                    }
            }
        }
        __syncthreads();
    }

    float* stage = (float*)sm;            // [128][132]
    #pragma unroll
    for (int fm = 0; fm < 2; fm++)
        #pragma unroll
        for (int fn = 0; fn < 8; fn++){
            int row = warp_m*32 + fm*16 + (lane>>2);
            int col = warp_n*64 + fn*8 + 2*(lane&3);
            *(float2*)&stage[row*132+col]     = make_float2(d[fm][fn][0], d[fm][fn][1]);
            *(float2*)&stage[(row+8)*132+col] = make_float2(d[fm][fn][2], d[fm][fn][3]);
        }
    __syncthreads();

    if (mode == 2 || mode == 5){
        int col = tid & 127, mr0 = tid >> 7;
        float ls = 0.f, ls2 = 0.f;
        #pragma unroll 8
        for (int it = 0; it < 64; it++){
            int m = it*2 + mr0;
            float v = stage[m*132 + col];
            size_t o = ((size_t)b*Mrows + m0 + m)*HWv + n0 + col;
            v += bias[m0+m] + resid[o];
            out[o] = v;
            ls += v; ls2 += v*v;
        }
        if (mode == 5){
            atomicAdd(&g_lnsum[(size_t)b*HWv + n0 + col], ls);
            atomicAdd(&g_lnsq [(size_t)b*HWv + n0 + col], ls2);
        }
    } else {  // mode 1
        int n = tid >> 1;
        int mh = (tid & 1) * 64;
        size_t ro = ((size_t)b*HWv + n0 + n)*Cv + m0 + mh;
        #pragma unroll
        for (int c8 = 0; c8 < 8; c8++){
            uint4 hp, lp;
            bf16* hh = (bf16*)&hp; bf16* ll = (bf16*)&lp;
            #pragma unroll
            for (int i = 0; i < 8; i++){
                int m = mh + c8*8 + i;
                float v = gelu_f(stage[m*132 + n] + bias[m0 + m]);
                split_bf16(v, hh[i], ll[i]);
            }
            *(uint4*)&oxh[ro + c8*8] = hp;
            *(uint4*)&oxl[ro + c8*8] = lp;
        }
    }
}

// ---------------- merged Wq+Wkv projection GEMM (flat grid, 2560 CTAs) -----------
__global__ __launch_bounds__(256,3) void gemm_qkv_kernel()
{
    extern __shared__ char sm[];
    uint32_t smb = smem_to_u32(sm);
    int tid = threadIdx.x, lane = tid & 31, warp = tid >> 5;
    int warp_m = warp & 3, warp_n = warp >> 2;

    const bf16 *Ah, *Al, *Bh, *Bl;
    int m0, n0, b, job;                      // job 0 = Wq, 1 = Wkv
    {
        int cta = blockIdx.x;
        if (cta < 512){
            job = 0; n0 = (cta & 31) << 7; m0 = ((cta >> 5) & 1) << 7; b = cta >> 6;
            Ah = g_w_h;          Al = g_w_l;
            Bh = g_xa_h + (size_t)b*HWv*Cv;  Bl = g_xa_l + (size_t)b*HWv*Cv;
        } else {
            int c2 = cta - 512;
            job = 1; n0 = (c2 & 31) << 7; m0 = ((c2 >> 5) & 3) << 7; b = c2 >> 7;
            Ah = g_w_h + 65536;  Al = g_w_l + 65536;
            Bh = g_xkv_h + (size_t)b*HWv*Cv; Bl = g_xkv_l + (size_t)b*HWv*Cv;
        }
    }

    float d[2][8][4];
    #pragma unroll
    for (int i=0;i<2;i++)
        #pragma unroll
        for (int j=0;j<8;j++)
            #pragma unroll
            for (int k=0;k<4;k++) d[i][j][k] = 0.f;

    int a_row = (lane & 7) + ((lane >> 3) & 1) * 8;
    int a_kc  = (lane >> 4) * 8;
    int b_row = (lane & 7) + (lane >> 4) * 8;
    int b_kc  = ((lane >> 3) & 1) * 8;

    for (int kt = 0; kt < 4; kt++){
        int k0 = kt*64;
        #pragma unroll
        for (int it = 0; it < 4; it++){
            int lin = tid + it*256;
            int row = lin >> 3, kk = lin & 7;
            uint32_t so = row*(RS*2) + kk*16;
            size_t ga = (size_t)(m0+row)*Cv + k0 + kk*8;
            size_t gb = (size_t)(n0+row)*Cv + k0 + kk*8;
            *(uint4*)(sm+OFF_AH+so) = *(const uint4*)(Ah+ga);
            *(uint4*)(sm+OFF_AL+so) = *(const uint4*)(Al+ga);
            *(uint4*)(sm+OFF_BH+so) = *(const uint4*)(Bh+gb);
            *(uint4*)(sm+OFF_BL+so) = *(const uint4*)(Bl+gb);
        }
        __syncthreads();
        #pragma unroll
        for (int k16 = 0; k16 < 4; k16++){
            uint32_t ah[2][4], al[2][4];
            #pragma unroll
            for (int fm = 0; fm < 2; fm++){
                int arow = warp_m*32 + fm*16 + a_row;
                uint32_t aaddr = smb + OFF_AH + arow*(RS*2) + (k16*16 + a_kc)*2;
                ldmatrix_x4(ah[fm], aaddr);
                ldmatrix_x4(al[fm], aaddr + (OFF_AL-OFF_AH));
            }
            #pragma unroll
            for (int half = 0; half < 2; half++){
                uint32_t bh[2][4], bl[2][4];
                #pragma unroll
                for (int p = 0; p < 2; p++){
                    int nrow = warp_n*64 + half*32 + p*16 + b_row;
                    uint32_t baddr = smb + OFF_BH + nrow*(RS*2) + (k16*16 + b_kc)*2;
                    ldmatrix_x4(bh[p], baddr);
                    ldmatrix_x4(bl[p], baddr + (OFF_BL-OFF_BH));
                }
                #pragma unroll
                for (int fm = 0; fm < 2; fm++)
                    #pragma unroll
                    for (int j = 0; j < 4; j++){
                        float* dd = d[fm][half*4+j];
                        uint32_t* fh = &bh[j>>1][(j&1)*2];
                        uint32_t* fl = &bl[j>>1][(j&1)*2];
                        mma_bf16(dd, ah[fm], fh[0], fh[1]);
                        mma_bf16(dd, ah[fm], fl[0], fl[1]);
                        mma_bf16(dd, al[fm], fh[0], fh[1]);
                    }
            }
        }
        __syncthreads();
    }

    float* stage = (float*)sm;
    #pragma unroll
    for (int fm = 0; fm < 2; fm++)
        #pragma unroll
        for (int fn = 0; fn < 8; fn++){
            int row = warp_m*32 + fm*16 + (lane>>2);
            int col = warp_n*64 + fn*8 + 2*(lane&3);
            *(float2*)&stage[row*132+col]     = make_float2(d[fm][fn][0], d[fm][fn][1]);
            *(float2*)&stage[(row+8)*132+col] = make_float2(d[fm][fn][2], d[fm][fn][3]);
        }
    __syncthreads();

    if (job == 0 || m0 < 256){
        // K-major bf16 hi/lo out + fused squared-row-sum atomics (q or k)
        bf16* oh  = (job == 0) ? g_qb_h : g_kb_h;
        bf16* ol  = (job == 0) ? g_qb_l : g_kb_l;
        float* nrm = (job == 0) ? g_qinv : g_kinv;
        int n2 = (tid & 63)*2, mr = tid >> 6;
        #pragma unroll 8
        for (int it = 0; it < 32; it++){
            int m = it*4 + mr;
            float v0 = stage[m*132 + n2], v1 = stage[m*132 + n2 + 1];
            bf16 hb[2], lb[2];
            split_bf16(v0, hb[0], lb[0]);
            split_bf16(v1, hb[1], lb[1]);
            size_t o = ((size_t)b*Cv + m0 + m)*HWv + n0 + n2;
            *(uint32_t*)&oh[o] = *(uint32_t*)hb;
            *(uint32_t*)&ol[o] = *(uint32_t*)lb;
            float p = v0*v0 + v1*v1;
            #pragma unroll
            for (int off = 16; off > 0; off >>= 1)
                p += __shfl_xor_sync(0xffffffffu, p, off);
            if (lane == 0) atomicAdd(&nrm[b*Cv + m0 + m], p);
        }
    } else {
        // v -> XT bf16 hi/lo [sb][hw][c]
        int n = tid >> 1;
        int mh = (tid & 1) * 64;
        size_t ro = ((size_t)b*HWv + n0 + n)*Cv + (m0 - 256) + mh;
        #pragma unroll
        for (int c8 = 0; c8 < 8; c8++){
            uint4 hp, lp;
            bf16* hh = (bf16*)&hp; bf16* ll = (bf16*)&lp;
            #pragma unroll
            for (int i = 0; i < 8; i++){
                int m = mh + c8*8 + i;
                split_bf16(stage[m*132 + n], hh[i], ll[i]);
            }
            *(uint4*)&g_vt_h[ro + c8*8] = hp;
            *(uint4*)&g_vt_l[ro + c8*8] = lp;
        }
    }
}

// ---------------- HMMA split-K raw S = q @ k^T  (8 splits over HW) ---------------
__global__ __launch_bounds__(256) void attn_s_kernel()
{
    __shared__ __align__(16) char sm[36864];
    uint32_t smb = smem_to_u32(sm);
    int tid = threadIdx.x, lane = tid & 31, warp = tid >> 5;
    int warp_m = warp & 3, warp_n = warp >> 2;
    int split = blockIdx.x;                      // 0..7
    int sn = blockIdx.y, s = sn >> 2, n = sn & 3;
    int b = blockIdx.z;

    const bf16* srcs[4];
    srcs[0] = g_qb_h + ((size_t)b*Cv + n*HDv) * HWv;
    srcs[1] = g_qb_l + ((size_t)b*Cv + n*HDv) * HWv;
    srcs[2] = g_kb_h + ((size_t)(s*Bv + b)*Cv + n*HDv) * HWv;
    srcs[3] = g_kb_l + ((size_t)(s*Bv + b)*Cv + n*HDv) * HWv;

    int a_row = (lane & 7) + ((lane >> 3) & 1) * 8;
    int a_kc  = (lane >> 4) * 8;
    int b_row = (lane & 7) + (lane >> 4) * 8;
    int b_kc  = ((lane >> 3) & 1) * 8;

    float d[4][4];
    #pragma unroll
    for (int i=0;i<4;i++)
        #pragma unroll
        for (int j=0;j<4;j++) d[i][j] = 0.f;

    for (int kc = 0; kc < 8; kc++){
        int hwb = split*512 + kc*64;
        #pragma unroll
        for (int arr = 0; arr < 4; arr++)
            #pragma unroll
            for (int hf = 0; hf < 2; hf++){
                int rem = tid + hf*256;
                int row = rem >> 3, c8 = rem & 7;
                *(uint4*)(sm + arr*9216 + row*144 + c8*16) =
                    *(const uint4*)(srcs[arr] + (size_t)row*HWv + hwb + c8*8);
            }
        __syncthreads();
        #pragma unroll
        for (int k16 = 0; k16 < 4; k16++){
            uint32_t ah[4], al[4];
            int arow = warp_m*16 + a_row;
            uint32_t abase = smb + arow*144 + (k16*16 + a_kc)*2;
            ldmatrix_x4(ah, abase);
            ldmatrix_x4(al, abase + 9216);
            #pragma unroll
            for (int p = 0; p < 2; p++){
                uint32_t bh[4], bl[4];
                int nrow = warp_n*32 + p*16 + b_row;
                uint32_t bbase = smb + 18432 + nrow*144 + (k16*16 + b_kc)*2;
                ldmatrix_x4(bh, bbase);
                ldmatrix_x4(bl, bbase + 9216);
                #pragma unroll
                for (int j = 0; j < 2; j++){
                    float* dd = d[p*2+j];
                    mma_bf16(dd, ah, bh[j*2], bh[j*2+1]);
                    mma_bf16(dd, ah, bl[j*2], bl[j*2+1]);
                    mma_bf16(dd, al, bh[j*2], bh[j*2+1]);
                }
            }
        }
        __syncthreads();
    }
    float* op = g_spart + ((((size_t)split*2 + s)*Bv + b)*NHv + n) * 4096;
    int r = warp_m*16 + (lane>>2);
    #pragma unroll
    for (int fn = 0; fn < 4; fn++){
        int col = warp_n*32 + fn*8 + 2*(lane&3);
        *(float2*)&op[r*64+col]     = make_float2(d[fn][0], d[fn][1]);
        *(float2*)&op[(r+8)*64+col] = make_float2(d[fn][2], d[fn][3]);
    }
}

// ---------------- sum partials, inv-norms inline, softmax, gate -> bf16 P --------
__global__ __launch_bounds__(256) void attn_softmax_kernel(const float* __restrict__ attn_scale)
{
    int n = blockIdx.x, b = blockIdx.y, s = blockIdx.z;
    __shared__ float S[64][65];
    __shared__ float qi[64], ki[64], rfac[64];
    int tid = threadIdx.x;
    if (tid < 64){
        qi[tid] = 1.f / fmaxf(sqrtf(g_qinv[b*Cv + n*HDv + tid]), 1e-12f);
        ki[tid] = 1.f / fmaxf(sqrtf(g_kinv[(s*Bv + b)*Cv + n*HDv + tid]), 1e-12f);
    }
    __syncthreads();
    size_t moff = (((size_t)s*Bv + b)*NHv + n) * 4096;
    for (int idx = tid; idx < 4096; idx += 256){
        int c = idx >> 6, dd = idx & 63;
        float a = 0.f;
        #pragma unroll
        for (int sp = 0; sp < 8; sp++)
            a += g_spart[((((size_t)sp*2 + s)*Bv + b)*NHv + n)*4096 + idx];
        S[c][dd] = a * qi[c] * ki[dd];
    }
    __syncthreads();
    if (tid < 64){
        int c = tid;
        float g = 1.f / (1.f + expf(-attn_scale[n]));
        float factor = (s == 0) ? g : (1.f - g);
        float mx = -1e30f;
        for (int dd = 0; dd < 64; dd++) mx = fmaxf(mx, S[c][dd]);
        float sum = 0.f;
        for (int dd = 0; dd < 64; dd++){ float e = expf(S[c][dd] - mx); S[c][dd] = e; sum += e; }
        rfac[c] = factor / sum;
    }
    __syncthreads();
    for (int idx = tid; idx < 4096; idx += 256){
        int c = idx >> 6, dd = idx & 63;
        bf16 h, l;
        split_bf16(S[c][dd] * rfac[c], h, l);
        g_ph[moff + idx] = h;
        g_pl[moff + idx] = l;
    }
}

// ---------------- HMMA qkv = Ptex@Vt + Pdep@Vd -> XT bf16 hi/lo ------------------
#define AVO_V 36864
#define AV_SMEM (36864 + 4*18432)
__global__ __launch_bounds__(256) void attn_av_kernel()
{
    extern __shared__ char sm[];
    uint32_t smb = smem_to_u32(sm);
    int tid = threadIdx.x, lane = tid & 31, warp = tid >> 5;
    int warp_m = warp & 3, warp_n = warp >> 2;
    int hw0 = blockIdx.x * 128;
    int n = blockIdx.y, b = blockIdx.z;

    size_t offT = (((size_t)0*Bv + b)*NHv + n) * 4096;
    size_t offD = (((size_t)1*Bv + b)*NHv + n) * 4096;
    const bf16* psrc[4] = {g_ph + offT, g_pl + offT, g_ph + offD, g_pl + offD};
    const bf16* vsrc[4];
    vsrc[0] = g_vt_h + (size_t)b*HWv*Cv;
    vsrc[1] = g_vt_l + (size_t)b*HWv*Cv;
    vsrc[2] = g_vt_h + (size_t)(Bv + b)*HWv*Cv;
    vsrc[3] = g_vt_l + (size_t)(Bv + b)*HWv*Cv;

    #pragma unroll
    for (int arr = 0; arr < 4; arr++)
        #pragma unroll
        for (int hf = 0; hf < 2; hf++){
            int rem = tid + hf*256;
            int row = rem >> 3, c8 = rem & 7;
            *(uint4*)(sm + arr*9216 + row*144 + c8*16) =
                *(const uint4*)(psrc[arr] + row*64 + c8*8);
        }
    #pragma unroll
    for (int arr = 0; arr < 4; arr++)
        #pragma unroll
        for (int hf = 0; hf < 4; hf++){
            int rem = tid + hf*256;
            int row = rem >> 3, c8 = rem & 7;
            *(uint4*)(sm + AVO_V + arr*18432 + row*144 + c8*16) =
                *(const uint4*)(vsrc[arr] + (size_t)(hw0+row)*Cv + n*HDv + c8*8);
        }
    __syncthreads();

    int a_row = (lane & 7) + ((lane >> 3) & 1) * 8;
    int a_kc  = (lane >> 4) * 8;
    int b_row = (lane & 7) + (lane >> 4) * 8;
    int b_kc  = ((lane >> 3) & 1) * 8;

    float d[8][4];
    #pragma unroll
    for (int i=0;i<8;i++)
        #pragma unroll
        for (int j=0;j<4;j++) d[i][j] = 0.f;

    #pragma unroll
    for (int k16 = 0; k16 < 4; k16++){
        uint32_t ath[4], atl[4], adh[4], adl[4];
        int arow = warp_m*16 + a_row;
        uint32_t abase = smb + arow*144 + (k16*16 + a_kc)*2;
        ldmatrix_x4(ath, abase);
        ldmatrix_x4(atl, abase + 9216);
        ldmatrix_x4(adh, abase + 18432);
        ldmatrix_x4(adl, abase + 27648);
        #pragma unroll
        for (int p = 0; p < 4; p++){
            uint32_t bth[4], btl[4], bdh[4], bdl[4];
            int nrow = warp_n*64 + p*16 + b_row;
            uint32_t bbase = smb + AVO_V + nrow*144 + (k16*16 + b_kc)*2;
            ldmatrix_x4(bth, bbase);
            ldmatrix_x4(btl, bbase + 18432);
            ldmatrix_x4(bdh, bbase + 36864);
            ldmatrix_x4(bdl, bbase + 55296);
            #pragma unroll
            for (int j = 0; j < 2; j++){
                float* dd = d[p*2+j];
                mma_bf16(dd, ath, bth[j*2], bth[j*2+1]);
                mma_bf16(dd, ath, btl[j*2], btl[j*2+1]);
                mma_bf16(dd, atl, bth[j*2], bth[j*2+1]);
                mma_bf16(dd, adh, bdh[j*2], bdh[j*2+1]);
                mma_bf16(dd, adh, bdl[j*2], bdl[j*2+1]);
                mma_bf16(dd, adl, bdh[j*2], bdh[j*2+1]);
            }
        }
    }
    __syncthreads();
    float* stage = (float*)sm;
    int r = warp_m*16 + (lane>>2);
    #pragma unroll
    for (int fn = 0; fn < 8; fn++){
        int col = warp_n*64 + fn*8 + 2*(lane&3);
        *(float2*)&stage[r*132+col]     = make_float2(d[fn][0], d[fn][1]);
        *(float2*)&stage[(r+8)*132+col] = make_float2(d[fn][2], d[fn][3]);
    }
    __syncthreads();
    int hw_l = tid >> 1, c0 = (tid & 1) * 32;
    #pragma unroll
    for (int q4 = 0; q4 < 4; q4++){
        uint4 hp, lp;
        bf16* hh = (bf16*)&hp; bf16* ll = (bf16*)&lp;
        #pragma unroll
        for (int i = 0; i < 8; i++){
            float v = stage[(c0 + q4*8 + i)*132 + hw_l];
            split_bf16(v, hh[i], ll[i]);
        }
        size_t ro = ((size_t)b*HWv + hw0 + hw_l)*Cv + n*HDv + c0 + q4*8;
        *(uint4*)&g_xqkv_h[ro] = hp;
        *(uint4*)&g_xqkv_l[ro] = lp;
    }
}

// ---------------- host launcher ----------------
extern "C" void kernel_launch(void* const* d_in, const int* in_sizes, int n_in,
                              void* d_out, int out_size)
{
    const float* img    = (const float*)d_in[0];
    const float* aux0   = (const float*)d_in[1];
    const float* aux1   = (const float*)d_in[2];
    const float* qlnw   = (const float*)d_in[3];
    const float* qlnb   = (const float*)d_in[4];
    const float* kvlnw  = (const float*)d_in[5];
    const float* kvlnb  = (const float*)d_in[6];
    const float* Wq     = (const float*)d_in[7];
    const float* Wkv    = (const float*)d_in[8];
    const float* Wo     = (const float*)d_in[9];
    const float* bo     = (const float*)d_in[10];
    const float* ascale = (const float*)d_in[11];
    const float* mlnw   = (const float*)d_in[12];
    const float* mlnb   = (const float*)d_in[13];
    const float* W1     = (const float*)d_in[14];
    const float* b1     = (const float*)d_in[15];
    const float* W2     = (const float*)d_in[16];
    const float* b2     = (const float*)d_in[17];

    bf16 *xa_h,*xa_l,*xkv_h,*xkv_l,*xqkv_h,*xqkv_l,*xh_h,*xh_l,*wh,*wl;
    float *xbuf,*qinv,*kinv,*lnsum,*lnsq;
    cudaGetSymbolAddress((void**)&xa_h,  g_xa_h);
    cudaGetSymbolAddress((void**)&xa_l,  g_xa_l);
    cudaGetSymbolAddress((void**)&xkv_h, g_xkv_h);
    cudaGetSymbolAddress((void**)&xkv_l, g_xkv_l);
    cudaGetSymbolAddress((void**)&xqkv_h,g_xqkv_h);
    cudaGetSymbolAddress((void**)&xqkv_l,g_xqkv_l);
    cudaGetSymbolAddress((void**)&xh_h,  g_xh_h);
    cudaGetSymbolAddress((void**)&xh_l,  g_xh_l);
    cudaGetSymbolAddress((void**)&wh,    g_w_h);
    cudaGetSymbolAddress((void**)&wl,    g_w_l);
    cudaGetSymbolAddress((void**)&xbuf,  g_x);
    cudaGetSymbolAddress((void**)&qinv,  g_qinv);
    cudaGetSymbolAddress((void**)&kinv,  g_kinv);
    cudaGetSymbolAddress((void**)&lnsum, g_lnsum);
    cudaGetSymbolAddress((void**)&lnsq,  g_lnsq);

    cudaFuncSetAttribute(gemm_kernel,
                         cudaFuncAttributeMaxDynamicSharedMemorySize, GEMM_SMEM);
    cudaFuncSetAttribute(gemm_qkv_kernel,
                         cudaFuncAttributeMaxDynamicSharedMemorySize, GEMM_SMEM);
    cudaFuncSetAttribute(attn_av_kernel,
                         cudaFuncAttributeMaxDynamicSharedMemorySize, AV_SMEM);

    const int WO_O = 196608, W1_O = 262144, W2_O = 327680;

    // 0. all weight conversions in one launch + zero accumulators
    wconv5_kernel<<<1536,256>>>(Wq, Wkv, Wo, W1, W2, wh, wl);
    cudaMemsetAsync(qinv, 0, Bv*Cv*sizeof(float));
    cudaMemsetAsync(kinv, 0, 2*Bv*Cv*sizeof(float));
    cudaMemsetAsync(lnsum, 0, Bv*HWv*sizeof(float));
    cudaMemsetAsync(lnsq,  0, Bv*HWv*sizeof(float));

    const int LNB = (Bv*HWv)/256;   // 128

    // 1. All three input LayerNorms in one launch
    ln3_kernel<<<dim3(LNB,3),256>>>(img, aux0, aux1, qlnw, qlnb, kvlnw, kvlnb,
                                    xa_h, xa_l, xkv_h, xkv_l);

    // 2. Merged Wq + Wkv projections (flat grid) with fused sq-sum atomics
    gemm_qkv_kernel<<<2560, 256, GEMM_SMEM>>>();

    // 3. Attention (HMMA; 8-way split-K S, inv-norms inline in softmax)
    attn_s_kernel      <<<dim3(8, 2*NHv, Bv), 256>>>();
    attn_softmax_kernel<<<dim3(NHv, Bv, 2),   256>>>(ascale);
    attn_av_kernel     <<<dim3(HWv/128, NHv, Bv), 256, AV_SMEM>>>();

    // 4. x = img + Wo@qkv + bo  (mode 5: + fused LN stats)
    gemm_kernel<<<dim3(32,2,Bv), 256, GEMM_SMEM>>>(wh+WO_O, wl+WO_O, xqkv_h, xqkv_l,
        xbuf, nullptr, nullptr, bo, img, 5, 256);

    // 5. MLP: single-pass LN apply, W1+gelu, W2+resid -> out
    ln_apply_kernel<<<LNB,256>>>(xbuf, mlnw, mlnb, xa_h, xa_l);
    gemm_kernel<<<dim3(32,2,Bv), 256, GEMM_SMEM>>>(wh+W1_O, wl+W1_O, xa_h, xa_l,
        nullptr, xh_h, xh_l, b1, nullptr, 1, 256);
    gemm_kernel<<<dim3(32,2,Bv), 256, GEMM_SMEM>>>(wh+W2_O, wl+W2_O, xh_h, xh_l,
        (float*)d_out, nullptr, nullptr, b2, xbuf, 2, 256);
}

// round 15
// speedup vs baseline: 2.0724x; 2.0724x over previous
#include <cuda_runtime.h>
#include <cuda_bf16.h>
#include <math.h>
#include <stdint.h>

#define Bv 8
#define Cv 256
#define HWv 4096
#define NHv 4
#define HDv 64

typedef __nv_bfloat16 bf16;

// ---------------- scratch (device globals; no allocations) ----------------
__device__ bf16 g_xa_h [Bv*HWv*Cv];
__device__ bf16 g_xa_l [Bv*HWv*Cv];
__device__ bf16 g_xkv_h[2*Bv*HWv*Cv];
__device__ bf16 g_xkv_l[2*Bv*HWv*Cv];
__device__ bf16 g_xqkv_h[Bv*HWv*Cv];
__device__ bf16 g_xqkv_l[Bv*HWv*Cv];
__device__ bf16 g_xh_h [Bv*HWv*Cv];
__device__ bf16 g_xh_l [Bv*HWv*Cv];
__device__ bf16 g_w_h[393216];
__device__ bf16 g_w_l[393216];
__device__ bf16 g_qb_h[Bv*Cv*HWv];         // q K-major [b][c][hw]
__device__ bf16 g_qb_l[Bv*Cv*HWv];
__device__ bf16 g_kb_h[2*Bv*Cv*HWv];       // k K-major [sb][c][hw]
__device__ bf16 g_kb_l[2*Bv*Cv*HWv];
__device__ bf16 g_vt_h[2*Bv*HWv*Cv];       // v transposed [sb][hw][c]
__device__ bf16 g_vt_l[2*Bv*HWv*Cv];
__device__ bf16 g_ph[2*Bv*NHv*HDv*HDv];
__device__ bf16 g_pl[2*Bv*NHv*HDv*HDv];
__device__ float g_x  [Bv*Cv*HWv];
__device__ float g_qinv[Bv*Cv];            // raw squared-sum accum
__device__ float g_kinv[2*Bv*Cv];
__device__ float g_lnsum[Bv*HWv];          // mlp-LN fused stats
__device__ float g_lnsq [Bv*HWv];
__device__ float g_spart[4*2*Bv*NHv*HDv*HDv];   // 4 splits

// ---------------- helpers ----------------
__device__ __forceinline__ uint32_t smem_to_u32(const void* p){
    uint32_t a;
    asm("{ .reg .u64 t; cvta.to.shared.u64 t, %1; cvt.u32.u64 %0, t; }" : "=r"(a) : "l"(p));
    return a;
}
__device__ __forceinline__ void ldmatrix_x4(uint32_t* r, uint32_t addr){
    asm volatile("ldmatrix.sync.aligned.m8n8.x4.shared.b16 {%0,%1,%2,%3}, [%4];"
        : "=r"(r[0]), "=r"(r[1]), "=r"(r[2]), "=r"(r[3]) : "r"(addr));
}
__device__ __forceinline__ void mma_bf16(float* d, const uint32_t* a, uint32_t b0, uint32_t b1){
    asm volatile("mma.sync.aligned.m16n8k16.row.col.f32.bf16.bf16.f32 "
        "{%0,%1,%2,%3}, {%4,%5,%6,%7}, {%8,%9}, {%0,%1,%2,%3};"
        : "+f"(d[0]), "+f"(d[1]), "+f"(d[2]), "+f"(d[3])
        : "r"(a[0]), "r"(a[1]), "r"(a[2]), "r"(a[3]), "r"(b0), "r"(b1));
}
__device__ __forceinline__ float gelu_f(float v){
    float c = v + 0.044715f*v*v*v;
    float t = tanhf(0.7978845608028654f * c);
    return 0.5f*v*(1.f+t);
}
__device__ __forceinline__ void split_bf16(float v, bf16& h, bf16& l){
    h = __float2bfloat16(v);
    l = __float2bfloat16(v - __bfloat162float(h));
}

// ---------------- all-5 weight conversions in one launch ----------------
__global__ void wconv5_kernel(const float* __restrict__ w0, const float* __restrict__ w1,
                              const float* __restrict__ w2, const float* __restrict__ w3,
                              const float* __restrict__ w4,
                              bf16* __restrict__ h, bf16* __restrict__ l){
    int i = blockIdx.x*256 + threadIdx.x;          // 0..393215
    const float* src; int j;
    if (i < 65536)       { src = w0; j = i; }
    else if (i < 196608) { src = w1; j = i - 65536; }
    else if (i < 262144) { src = w2; j = i - 196608; }
    else if (i < 327680) { src = w3; j = i - 262144; }
    else                 { src = w4; j = i - 327680; }
    bf16 hh, ll; split_bf16(src[j], hh, ll);
    h[i] = hh; l[i] = ll;
}

// ---------------- merged LayerNorm (3 input tensors) -> XT bf16 hi/lo ------------
__global__ __launch_bounds__(256) void ln3_kernel(
        const float* __restrict__ img, const float* __restrict__ aux0,
        const float* __restrict__ aux1,
        const float* __restrict__ qw, const float* __restrict__ qb,
        const float* __restrict__ kw, const float* __restrict__ kb,
        bf16* __restrict__ xa_h, bf16* __restrict__ xa_l,
        bf16* __restrict__ xkv_h, bf16* __restrict__ xkv_l)
{
    int which = blockIdx.y;
    const float* x = (which == 0) ? img : (which == 1) ? aux0 : aux1;
    const float* w = (which == 0) ? qw : kw;
    const float* bias = (which == 0) ? qb : kb;
    bf16* oh = (which == 0) ? xa_h : xkv_h + (size_t)(which-1)*Bv*HWv*Cv;
    bf16* ol = (which == 0) ? xa_l : xkv_l + (size_t)(which-1)*Bv*HWv*Cv;

    int idx = blockIdx.x*blockDim.x + threadIdx.x;
    int b = idx / HWv, hw = idx % HWv;
    const float* xb = x + (size_t)b*Cv*HWv + hw;
    float s = 0.f, s2 = 0.f;
    #pragma unroll 8
    for (int c = 0; c < Cv; c++){ float v = xb[(size_t)c*HWv]; s += v; s2 += v*v; }
    float m   = s * (1.f/Cv);
    float var = s2 * (1.f/Cv) - m*m;
    float inv = rsqrtf(var + 1e-5f);
    size_t base = ((size_t)b*HWv + hw) * Cv;
    for (int c8 = 0; c8 < Cv/8; c8++){
        uint4 hp, lp;
        bf16* hh = (bf16*)&hp; bf16* ll = (bf16*)&lp;
        #pragma unroll
        for (int i = 0; i < 8; i++){
            int c = c8*8 + i;
            float v = (xb[(size_t)c*HWv] - m) * inv * w[c] + bias[c];
            split_bf16(v, hh[i], ll[i]);
        }
        *(uint4*)&oh[base + c8*8] = hp;
        *(uint4*)&ol[base + c8*8] = lp;
    }
}

// ---------------- single-pass LN apply using fused stats (mlp LN) ----------------
__global__ __launch_bounds__(256) void ln_apply_kernel(const float* __restrict__ x,
        const float* __restrict__ w, const float* __restrict__ bias,
        bf16* __restrict__ oh, bf16* __restrict__ ol)
{
    int idx = blockIdx.x*blockDim.x + threadIdx.x;
    int b = idx / HWv, hw = idx % HWv;
    float s  = g_lnsum[idx];
    float s2 = g_lnsq[idx];
    float m   = s * (1.f/Cv);
    float var = s2 * (1.f/Cv) - m*m;
    float inv = rsqrtf(var + 1e-5f);
    const float* xb = x + (size_t)b*Cv*HWv + hw;
    size_t base = ((size_t)b*HWv + hw) * Cv;
    for (int c8 = 0; c8 < Cv/8; c8++){
        uint4 hp, lp;
        bf16* hh = (bf16*)&hp; bf16* ll = (bf16*)&lp;
        #pragma unroll
        for (int i = 0; i < 8; i++){
            int c = c8*8 + i;
            float v = (xb[(size_t)c*HWv] - m) * inv * w[c] + bias[c];
            split_bf16(v, hh[i], ll[i]);
        }
        *(uint4*)&oh[base + c8*8] = hp;
        *(uint4*)&ol[base + c8*8] = lp;
    }
}

// ---------------- HMMA bf16x3 GEMM (R6-proven mainloop, occ 2) -------------------
// mode 1: oxh/oxl bf16 XT [b][hw][c], +bias, gelu
// mode 2: out fp32, +bias +resid
// mode 5: mode 2 + fused LN stats atomics into g_lnsum/g_lnsq
#define RS 72
#define OFF_AH 0
#define OFF_AL 18432
#define OFF_BH 36864
#define OFF_BL 55296
#define GEMM_SMEM 73728

__global__ __launch_bounds__(256,2) void gemm_kernel(
    const bf16* __restrict__ Ah, const bf16* __restrict__ Al,
    const bf16* __restrict__ Bh, const bf16* __restrict__ Bl,
    float* __restrict__ out, bf16* __restrict__ oxh, bf16* __restrict__ oxl,
    const float* __restrict__ bias, const float* __restrict__ resid,
    int mode, int Mrows)
{
    extern __shared__ char sm[];
    uint32_t smb = smem_to_u32(sm);
    int tid = threadIdx.x, lane = tid & 31, warp = tid >> 5;
    int warp_m = warp & 3, warp_n = warp >> 2;
    int n0 = blockIdx.x*128, m0 = blockIdx.y*128, b = blockIdx.z;
    const bf16* Bhb = Bh + (size_t)b*HWv*Cv;
    const bf16* Blb = Bl + (size_t)b*HWv*Cv;

    float d[2][8][4];
    #pragma unroll
    for (int i=0;i<2;i++)
        #pragma unroll
        for (int j=0;j<8;j++)
            #pragma unroll
            for (int k=0;k<4;k++) d[i][j][k] = 0.f;

    int a_row = (lane & 7) + ((lane >> 3) & 1) * 8;
    int a_kc  = (lane >> 4) * 8;
    int b_row = (lane & 7) + (lane >> 4) * 8;
    int b_kc  = ((lane >> 3) & 1) * 8;

    for (int kt = 0; kt < 4; kt++){
        int k0 = kt*64;
        #pragma unroll
        for (int it = 0; it < 4; it++){
            int lin = tid + it*256;
            int row = lin >> 3, kk = lin & 7;
            uint32_t so = row*(RS*2) + kk*16;
            size_t ga = (size_t)(m0+row)*Cv + k0 + kk*8;
            size_t gb = (size_t)(n0+row)*Cv + k0 + kk*8;
            *(uint4*)(sm+OFF_AH+so) = *(const uint4*)(Ah +ga);
            *(uint4*)(sm+OFF_AL+so) = *(const uint4*)(Al +ga);
            *(uint4*)(sm+OFF_BH+so) = *(const uint4*)(Bhb+gb);
            *(uint4*)(sm+OFF_BL+so) = *(const uint4*)(Blb+gb);
        }
        __syncthreads();
        #pragma unroll
        for (int k16 = 0; k16 < 4; k16++){
            uint32_t ah[2][4], al[2][4];
            #pragma unroll
            for (int fm = 0; fm < 2; fm++){
                int arow = warp_m*32 + fm*16 + a_row;
                uint32_t aaddr = smb + OFF_AH + arow*(RS*2) + (k16*16 + a_kc)*2;
                ldmatrix_x4(ah[fm], aaddr);
                ldmatrix_x4(al[fm], aaddr + (OFF_AL-OFF_AH));
            }
            #pragma unroll
            for (int half = 0; half < 2; half++){
                uint32_t bh[2][4], bl[2][4];
                #pragma unroll
                for (int p = 0; p < 2; p++){
                    int nrow = warp_n*64 + half*32 + p*16 + b_row;
                    uint32_t baddr = smb + OFF_BH + nrow*(RS*2) + (k16*16 + b_kc)*2;
                    ldmatrix_x4(bh[p], baddr);
                    ldmatrix_x4(bl[p], baddr + (OFF_BL-OFF_BH));
                }
                #pragma unroll
                for (int fm = 0; fm < 2; fm++)
                    #pragma unroll
                    for (int j = 0; j < 4; j++){
                        float* dd = d[fm][half*4+j];
                        uint32_t* fh = &bh[j>>1][(j&1)*2];
                        uint32_t* fl = &bl[j>>1][(j&1)*2];
                        mma_bf16(dd, ah[fm], fh[0], fh[1]);
                        mma_bf16(dd, ah[fm], fl[0], fl[1]);
                        mma_bf16(dd, al[fm], fh[0], fh[1]);
                    }
            }
        }
        __syncthreads();
    }

    float* stage = (float*)sm;            // [128][132]
    #pragma unroll
    for (int fm = 0; fm < 2; fm++)
        #pragma unroll
        for (int fn = 0; fn < 8; fn++){
            int row = warp_m*32 + fm*16 + (lane>>2);
            int col = warp_n*64 + fn*8 + 2*(lane&3);
            *(float2*)&stage[row*132+col]     = make_float2(d[fm][fn][0], d[fm][fn][1]);
            *(float2*)&stage[(row+8)*132+col] = make_float2(d[fm][fn][2], d[fm][fn][3]);
        }
    __syncthreads();

    if (mode == 2 || mode == 5){
        int col = tid & 127, mr0 = tid >> 7;
        float ls = 0.f, ls2 = 0.f;
        #pragma unroll 8
        for (int it = 0; it < 64; it++){
            int m = it*2 + mr0;
            float v = stage[m*132 + col];
            size_t o = ((size_t)b*Mrows + m0 + m)*HWv + n0 + col;
            v += bias[m0+m] + resid[o];
            out[o] = v;
            ls += v; ls2 += v*v;
        }
        if (mode == 5){
            atomicAdd(&g_lnsum[(size_t)b*HWv + n0 + col], ls);
            atomicAdd(&g_lnsq [(size_t)b*HWv + n0 + col], ls2);
        }
    } else {  // mode 1
        int n = tid >> 1;
        int mh = (tid & 1) * 64;
        size_t ro = ((size_t)b*HWv + n0 + n)*Cv + m0 + mh;
        #pragma unroll
        for (int c8 = 0; c8 < 8; c8++){
            uint4 hp, lp;
            bf16* hh = (bf16*)&hp; bf16* ll = (bf16*)&lp;
            #pragma unroll
            for (int i = 0; i < 8; i++){
                int m = mh + c8*8 + i;
                float v = gelu_f(stage[m*132 + n] + bias[m0 + m]);
                split_bf16(v, hh[i], ll[i]);
            }
            *(uint4*)&oxh[ro + c8*8] = hp;
            *(uint4*)&oxl[ro + c8*8] = lp;
        }
    }
}

// ---------------- merged Wq+Wkv projection GEMM (flat grid, 2560 CTAs) -----------
__global__ __launch_bounds__(256,2) void gemm_qkv_kernel()
{
    extern __shared__ char sm[];
    uint32_t smb = smem_to_u32(sm);
    int tid = threadIdx.x, lane = tid & 31, warp = tid >> 5;
    int warp_m = warp & 3, warp_n = warp >> 2;

    const bf16 *Ah, *Al, *Bh, *Bl;
    int m0, n0, b, job;                      // job 0 = Wq, 1 = Wkv
    {
        int cta = blockIdx.x;
        if (cta < 512){
            job = 0; n0 = (cta & 31) << 7; m0 = ((cta >> 5) & 1) << 7; b = cta >> 6;
            Ah = g_w_h;          Al = g_w_l;
            Bh = g_xa_h + (size_t)b*HWv*Cv;  Bl = g_xa_l + (size_t)b*HWv*Cv;
        } else {
            int c2 = cta - 512;
            job = 1; n0 = (c2 & 31) << 7; m0 = ((c2 >> 5) & 3) << 7; b = c2 >> 7;
            Ah = g_w_h + 65536;  Al = g_w_l + 65536;
            Bh = g_xkv_h + (size_t)b*HWv*Cv; Bl = g_xkv_l + (size_t)b*HWv*Cv;
        }
    }

    float d[2][8][4];
    #pragma unroll
    for (int i=0;i<2;i++)
        #pragma unroll
        for (int j=0;j<8;j++)
            #pragma unroll
            for (int k=0;k<4;k++) d[i][j][k] = 0.f;

    int a_row = (lane & 7) + ((lane >> 3) & 1) * 8;
    int a_kc  = (lane >> 4) * 8;
    int b_row = (lane & 7) + (lane >> 4) * 8;
    int b_kc  = ((lane >> 3) & 1) * 8;

    for (int kt = 0; kt < 4; kt++){
        int k0 = kt*64;
        #pragma unroll
        for (int it = 0; it < 4; it++){
            int lin = tid + it*256;
            int row = lin >> 3, kk = lin & 7;
            uint32_t so = row*(RS*2) + kk*16;
            size_t ga = (size_t)(m0+row)*Cv + k0 + kk*8;
            size_t gb = (size_t)(n0+row)*Cv + k0 + kk*8;
            *(uint4*)(sm+OFF_AH+so) = *(const uint4*)(Ah+ga);
            *(uint4*)(sm+OFF_AL+so) = *(const uint4*)(Al+ga);
            *(uint4*)(sm+OFF_BH+so) = *(const uint4*)(Bh+gb);
            *(uint4*)(sm+OFF_BL+so) = *(const uint4*)(Bl+gb);
        }
        __syncthreads();
        #pragma unroll
        for (int k16 = 0; k16 < 4; k16++){
            uint32_t ah[2][4], al[2][4];
            #pragma unroll
            for (int fm = 0; fm < 2; fm++){
                int arow = warp_m*32 + fm*16 + a_row;
                uint32_t aaddr = smb + OFF_AH + arow*(RS*2) + (k16*16 + a_kc)*2;
                ldmatrix_x4(ah[fm], aaddr);
                ldmatrix_x4(al[fm], aaddr + (OFF_AL-OFF_AH));
            }
            #pragma unroll
            for (int half = 0; half < 2; half++){
                uint32_t bh[2][4], bl[2][4];
                #pragma unroll
                for (int p = 0; p < 2; p++){
                    int nrow = warp_n*64 + half*32 + p*16 + b_row;
                    uint32_t baddr = smb + OFF_BH + nrow*(RS*2) + (k16*16 + b_kc)*2;
                    ldmatrix_x4(bh[p], baddr);
                    ldmatrix_x4(bl[p], baddr + (OFF_BL-OFF_BH));
                }
                #pragma unroll
                for (int fm = 0; fm < 2; fm++)
                    #pragma unroll
                    for (int j = 0; j < 4; j++){
                        float* dd = d[fm][half*4+j];
                        uint32_t* fh = &bh[j>>1][(j&1)*2];
                        uint32_t* fl = &bl[j>>1][(j&1)*2];
                        mma_bf16(dd, ah[fm], fh[0], fh[1]);
                        mma_bf16(dd, ah[fm], fl[0], fl[1]);
                        mma_bf16(dd, al[fm], fh[0], fh[1]);
                    }
            }
        }
        __syncthreads();
    }

    float* stage = (float*)sm;
    #pragma unroll
    for (int fm = 0; fm < 2; fm++)
        #pragma unroll
        for (int fn = 0; fn < 8; fn++){
            int row = warp_m*32 + fm*16 + (lane>>2);
            int col = warp_n*64 + fn*8 + 2*(lane&3);
            *(float2*)&stage[row*132+col]     = make_float2(d[fm][fn][0], d[fm][fn][1]);
            *(float2*)&stage[(row+8)*132+col] = make_float2(d[fm][fn][2], d[fm][fn][3]);
        }
    __syncthreads();

    if (job == 0 || m0 < 256){
        // K-major bf16 hi/lo out + fused squared-row-sum atomics (q or k)
        bf16* oh  = (job == 0) ? g_qb_h : g_kb_h;
        bf16* ol  = (job == 0) ? g_qb_l : g_kb_l;
        float* nrm = (job == 0) ? g_qinv : g_kinv;
        int n2 = (tid & 63)*2, mr = tid >> 6;
        #pragma unroll 8
        for (int it = 0; it < 32; it++){
            int m = it*4 + mr;
            float v0 = stage[m*132 + n2], v1 = stage[m*132 + n2 + 1];
            bf16 hb[2], lb[2];
            split_bf16(v0, hb[0], lb[0]);
            split_bf16(v1, hb[1], lb[1]);
            size_t o = ((size_t)b*Cv + m0 + m)*HWv + n0 + n2;
            *(uint32_t*)&oh[o] = *(uint32_t*)hb;
            *(uint32_t*)&ol[o] = *(uint32_t*)lb;
            float p = v0*v0 + v1*v1;
            #pragma unroll
            for (int off = 16; off > 0; off >>= 1)
                p += __shfl_xor_sync(0xffffffffu, p, off);
            if (lane == 0) atomicAdd(&nrm[b*Cv + m0 + m], p);
        }
    } else {
        // v -> XT bf16 hi/lo [sb][hw][c]
        int n = tid >> 1;
        int mh = (tid & 1) * 64;
        size_t ro = ((size_t)b*HWv + n0 + n)*Cv + (m0 - 256) + mh;
        #pragma unroll
        for (int c8 = 0; c8 < 8; c8++){
            uint4 hp, lp;
            bf16* hh = (bf16*)&hp; bf16* ll = (bf16*)&lp;
            #pragma unroll
            for (int i = 0; i < 8; i++){
                int m = mh + c8*8 + i;
                split_bf16(stage[m*132 + n], hh[i], ll[i]);
            }
            *(uint4*)&g_vt_h[ro + c8*8] = hp;
            *(uint4*)&g_vt_l[ro + c8*8] = lp;
        }
    }
}

// ---------------- HMMA split-K raw S = q @ k^T  (4 splits over HW) ---------------
__global__ __launch_bounds__(256) void attn_s_kernel()
{
    __shared__ __align__(16) char sm[36864];
    uint32_t smb = smem_to_u32(sm);
    int tid = threadIdx.x, lane = tid & 31, warp = tid >> 5;
    int warp_m = warp & 3, warp_n = warp >> 2;
    int split = blockIdx.x;                      // 0..3
    int sn = blockIdx.y, s = sn >> 2, n = sn & 3;
    int b = blockIdx.z;

    const bf16* srcs[4];
    srcs[0] = g_qb_h + ((size_t)b*Cv + n*HDv) * HWv;
    srcs[1] = g_qb_l + ((size_t)b*Cv + n*HDv) * HWv;
    srcs[2] = g_kb_h + ((size_t)(s*Bv + b)*Cv + n*HDv) * HWv;
    srcs[3] = g_kb_l + ((size_t)(s*Bv + b)*Cv + n*HDv) * HWv;

    int a_row = (lane & 7) + ((lane >> 3) & 1) * 8;
    int a_kc  = (lane >> 4) * 8;
    int b_row = (lane & 7) + (lane >> 4) * 8;
    int b_kc  = ((lane >> 3) & 1) * 8;

    float d[4][4];
    #pragma unroll
    for (int i=0;i<4;i++)
        #pragma unroll
        for (int j=0;j<4;j++) d[i][j] = 0.f;

    for (int kc = 0; kc < 16; kc++){
        int hwb = split*1024 + kc*64;
        #pragma unroll
        for (int arr = 0; arr < 4; arr++)
            #pragma unroll
            for (int hf = 0; hf < 2; hf++){
                int rem = tid + hf*256;
                int row = rem >> 3, c8 = rem & 7;
                *(uint4*)(sm + arr*9216 + row*144 + c8*16) =
                    *(const uint4*)(srcs[arr] + (size_t)row*HWv + hwb + c8*8);
            }
        __syncthreads();
        #pragma unroll
        for (int k16 = 0; k16 < 4; k16++){
            uint32_t ah[4], al[4];
            int arow = warp_m*16 + a_row;
            uint32_t abase = smb + arow*144 + (k16*16 + a_kc)*2;
            ldmatrix_x4(ah, abase);
            ldmatrix_x4(al, abase + 9216);
            #pragma unroll
            for (int p = 0; p < 2; p++){
                uint32_t bh[4], bl[4];
                int nrow = warp_n*32 + p*16 + b_row;
                uint32_t bbase = smb + 18432 + nrow*144 + (k16*16 + b_kc)*2;
                ldmatrix_x4(bh, bbase);
                ldmatrix_x4(bl, bbase + 9216);
                #pragma unroll
                for (int j = 0; j < 2; j++){
                    float* dd = d[p*2+j];
                    mma_bf16(dd, ah, bh[j*2], bh[j*2+1]);
                    mma_bf16(dd, ah, bl[j*2], bl[j*2+1]);
                    mma_bf16(dd, al, bh[j*2], bh[j*2+1]);
                }
            }
        }
        __syncthreads();
    }
    float* op = g_spart + ((((size_t)split*2 + s)*Bv + b)*NHv + n) * 4096;
    int r = warp_m*16 + (lane>>2);
    #pragma unroll
    for (int fn = 0; fn < 4; fn++){
        int col = warp_n*32 + fn*8 + 2*(lane&3);
        *(float2*)&op[r*64+col]     = make_float2(d[fn][0], d[fn][1]);
        *(float2*)&op[(r+8)*64+col] = make_float2(d[fn][2], d[fn][3]);
    }
}

// ---------------- sum partials, inv-norms inline, softmax, gate -> bf16 P --------
__global__ __launch_bounds__(256) void attn_softmax_kernel(const float* __restrict__ attn_scale)
{
    int n = blockIdx.x, b = blockIdx.y, s = blockIdx.z;
    __shared__ float S[64][65];
    __shared__ float qi[64], ki[64], rfac[64];
    int tid = threadIdx.x;
    if (tid < 64){
        qi[tid] = 1.f / fmaxf(sqrtf(g_qinv[b*Cv + n*HDv + tid]), 1e-12f);
        ki[tid] = 1.f / fmaxf(sqrtf(g_kinv[(s*Bv + b)*Cv + n*HDv + tid]), 1e-12f);
    }
    __syncthreads();
    size_t moff = (((size_t)s*Bv + b)*NHv + n) * 4096;
    for (int idx = tid; idx < 4096; idx += 256){
        int c = idx >> 6, dd = idx & 63;
        float a = 0.f;
        #pragma unroll
        for (int sp = 0; sp < 4; sp++)
            a += g_spart[((((size_t)sp*2 + s)*Bv + b)*NHv + n)*4096 + idx];
        S[c][dd] = a * qi[c] * ki[dd];
    }
    __syncthreads();
    if (tid < 64){
        int c = tid;
        float g = 1.f / (1.f + expf(-attn_scale[n]));
        float factor = (s == 0) ? g : (1.f - g);
        float mx = -1e30f;
        for (int dd = 0; dd < 64; dd++) mx = fmaxf(mx, S[c][dd]);
        float sum = 0.f;
        for (int dd = 0; dd < 64; dd++){ float e = expf(S[c][dd] - mx); S[c][dd] = e; sum += e; }
        rfac[c] = factor / sum;
    }
    __syncthreads();
    for (int idx = tid; idx < 4096; idx += 256){
        int c = idx >> 6, dd = idx & 63;
        bf16 h, l;
        split_bf16(S[c][dd] * rfac[c], h, l);
        g_ph[moff + idx] = h;
        g_pl[moff + idx] = l;
    }
}

// ---------------- HMMA qkv = Ptex@Vt + Pdep@Vd -> XT bf16 hi/lo ------------------
#define AVO_V 36864
#define AV_SMEM (36864 + 4*18432)
__global__ __launch_bounds__(256) void attn_av_kernel()
{
    extern __shared__ char sm[];
    uint32_t smb = smem_to_u32(sm);
    int tid = threadIdx.x, lane = tid & 31, warp = tid >> 5;
    int warp_m = warp & 3, warp_n = warp >> 2;
    int hw0 = blockIdx.x * 128;
    int n = blockIdx.y, b = blockIdx.z;

    size_t offT = (((size_t)0*Bv + b)*NHv + n) * 4096;
    size_t offD = (((size_t)1*Bv + b)*NHv + n) * 4096;
    const bf16* psrc[4] = {g_ph + offT, g_pl + offT, g_ph + offD, g_pl + offD};
    const bf16* vsrc[4];
    vsrc[0] = g_vt_h + (size_t)b*HWv*Cv;
    vsrc[1] = g_vt_l + (size_t)b*HWv*Cv;
    vsrc[2] = g_vt_h + (size_t)(Bv + b)*HWv*Cv;
    vsrc[3] = g_vt_l + (size_t)(Bv + b)*HWv*Cv;

    #pragma unroll
    for (int arr = 0; arr < 4; arr++)
        #pragma unroll
        for (int hf = 0; hf < 2; hf++){
            int rem = tid + hf*256;
            int row = rem >> 3, c8 = rem & 7;
            *(uint4*)(sm + arr*9216 + row*144 + c8*16) =
                *(const uint4*)(psrc[arr] + row*64 + c8*8);
        }
    #pragma unroll
    for (int arr = 0; arr < 4; arr++)
        #pragma unroll
        for (int hf = 0; hf < 4; hf++){
            int rem = tid + hf*256;
            int row = rem >> 3, c8 = rem & 7;
            *(uint4*)(sm + AVO_V + arr*18432 + row*144 + c8*16) =
                *(const uint4*)(vsrc[arr] + (size_t)(hw0+row)*Cv + n*HDv + c8*8);
        }
    __syncthreads();

    int a_row = (lane & 7) + ((lane >> 3) & 1) * 8;
    int a_kc  = (lane >> 4) * 8;
    int b_row = (lane & 7) + (lane >> 4) * 8;
    int b_kc  = ((lane >> 3) & 1) * 8;

    float d[8][4];
    #pragma unroll
    for (int i=0;i<8;i++)
        #pragma unroll
        for (int j=0;j<4;j++) d[i][j] = 0.f;

    #pragma unroll
    for (int k16 = 0; k16 < 4; k16++){
        uint32_t ath[4], atl[4], adh[4], adl[4];
        int arow = warp_m*16 + a_row;
        uint32_t abase = smb + arow*144 + (k16*16 + a_kc)*2;
        ldmatrix_x4(ath, abase);
        ldmatrix_x4(atl, abase + 9216);
        ldmatrix_x4(adh, abase + 18432);
        ldmatrix_x4(adl, abase + 27648);
        #pragma unroll
        for (int p = 0; p < 4; p++){
            uint32_t bth[4], btl[4], bdh[4], bdl[4];
            int nrow = warp_n*64 + p*16 + b_row;
            uint32_t bbase = smb + AVO_V + nrow*144 + (k16*16 + b_kc)*2;
            ldmatrix_x4(bth, bbase);
            ldmatrix_x4(btl, bbase + 18432);
            ldmatrix_x4(bdh, bbase + 36864);
            ldmatrix_x4(bdl, bbase + 55296);
            #pragma unroll
            for (int j = 0; j < 2; j++){
                float* dd = d[p*2+j];
                mma_bf16(dd, ath, bth[j*2], bth[j*2+1]);
                mma_bf16(dd, ath, btl[j*2], btl[j*2+1]);
                mma_bf16(dd, atl, bth[j*2], bth[j*2+1]);
                mma_bf16(dd, adh, bdh[j*2], bdh[j*2+1]);
                mma_bf16(dd, adh, bdl[j*2], bdl[j*2+1]);
                mma_bf16(dd, adl, bdh[j*2], bdh[j*2+1]);
            }
        }
    }
    __syncthreads();
    float* stage = (float*)sm;
    int r = warp_m*16 + (lane>>2);
    #pragma unroll
    for (int fn = 0; fn < 8; fn++){
        int col = warp_n*64 + fn*8 + 2*(lane&3);
        *(float2*)&stage[r*132+col]     = make_float2(d[fn][0], d[fn][1]);
        *(float2*)&stage[(r+8)*132+col] = make_float2(d[fn][2], d[fn][3]);
    }
    __syncthreads();
    int hw_l = tid >> 1, c0 = (tid & 1) * 32;
    #pragma unroll
    for (int q4 = 0; q4 < 4; q4++){
        uint4 hp, lp;
        bf16* hh = (bf16*)&hp; bf16* ll = (bf16*)&lp;
        #pragma unroll
        for (int i = 0; i < 8; i++){
            float v = stage[(c0 + q4*8 + i)*132 + hw_l];
            split_bf16(v, hh[i], ll[i]);
        }
        size_t ro = ((size_t)b*HWv + hw0 + hw_l)*Cv + n*HDv + c0 + q4*8;
        *(uint4*)&g_xqkv_h[ro] = hp;
        *(uint4*)&g_xqkv_l[ro] = lp;
    }
}

// ---------------- host launcher ----------------
extern "C" void kernel_launch(void* const* d_in, const int* in_sizes, int n_in,
                              void* d_out, int out_size)
{
    const float* img    = (const float*)d_in[0];
    const float* aux0   = (const float*)d_in[1];
    const float* aux1   = (const float*)d_in[2];
    const float* qlnw   = (const float*)d_in[3];
    const float* qlnb   = (const float*)d_in[4];
    const float* kvlnw  = (const float*)d_in[5];
    const float* kvlnb  = (const float*)d_in[6];
    const float* Wq     = (const float*)d_in[7];
    const float* Wkv    = (const float*)d_in[8];
    const float* Wo     = (const float*)d_in[9];
    const float* bo     = (const float*)d_in[10];
    const float* ascale = (const float*)d_in[11];
    const float* mlnw   = (const float*)d_in[12];
    const float* mlnb   = (const float*)d_in[13];
    const float* W1     = (const float*)d_in[14];
    const float* b1     = (const float*)d_in[15];
    const float* W2     = (const float*)d_in[16];
    const float* b2     = (const float*)d_in[17];

    bf16 *xa_h,*xa_l,*xkv_h,*xkv_l,*xqkv_h,*xqkv_l,*xh_h,*xh_l,*wh,*wl;
    float *xbuf,*qinv,*kinv,*lnsum,*lnsq;
    cudaGetSymbolAddress((void**)&xa_h,  g_xa_h);
    cudaGetSymbolAddress((void**)&xa_l,  g_xa_l);
    cudaGetSymbolAddress((void**)&xkv_h, g_xkv_h);
    cudaGetSymbolAddress((void**)&xkv_l, g_xkv_l);
    cudaGetSymbolAddress((void**)&xqkv_h,g_xqkv_h);
    cudaGetSymbolAddress((void**)&xqkv_l,g_xqkv_l);
    cudaGetSymbolAddress((void**)&xh_h,  g_xh_h);
    cudaGetSymbolAddress((void**)&xh_l,  g_xh_l);
    cudaGetSymbolAddress((void**)&wh,    g_w_h);
    cudaGetSymbolAddress((void**)&wl,    g_w_l);
    cudaGetSymbolAddress((void**)&xbuf,  g_x);
    cudaGetSymbolAddress((void**)&qinv,  g_qinv);
    cudaGetSymbolAddress((void**)&kinv,  g_kinv);
    cudaGetSymbolAddress((void**)&lnsum, g_lnsum);
    cudaGetSymbolAddress((void**)&lnsq,  g_lnsq);

    cudaFuncSetAttribute(gemm_kernel,
                         cudaFuncAttributeMaxDynamicSharedMemorySize, GEMM_SMEM);
    cudaFuncSetAttribute(gemm_qkv_kernel,
                         cudaFuncAttributeMaxDynamicSharedMemorySize, GEMM_SMEM);
    cudaFuncSetAttribute(attn_av_kernel,
                         cudaFuncAttributeMaxDynamicSharedMemorySize, AV_SMEM);

    const int WO_O = 196608, W1_O = 262144, W2_O = 327680;

    // 0. all weight conversions in one launch + zero accumulators
    wconv5_kernel<<<1536,256>>>(Wq, Wkv, Wo, W1, W2, wh, wl);
    cudaMemsetAsync(qinv, 0, Bv*Cv*sizeof(float));
    cudaMemsetAsync(kinv, 0, 2*Bv*Cv*sizeof(float));
    cudaMemsetAsync(lnsum, 0, Bv*HWv*sizeof(float));
    cudaMemsetAsync(lnsq,  0, Bv*HWv*sizeof(float));

    const int LNB = (Bv*HWv)/256;   // 128

    // 1. All three input LayerNorms in one launch
    ln3_kernel<<<dim3(LNB,3),256>>>(img, aux0, aux1, qlnw, qlnb, kvlnw, kvlnb,
                                    xa_h, xa_l, xkv_h, xkv_l);

    // 2. Merged Wq + Wkv projections (flat grid) with fused sq-sum atomics
    gemm_qkv_kernel<<<2560, 256, GEMM_SMEM>>>();

    // 3. Attention (HMMA; 4-way split-K S, inv-norms inline in softmax)
    attn_s_kernel      <<<dim3(4, 2*NHv, Bv), 256>>>();
    attn_softmax_kernel<<<dim3(NHv, Bv, 2),   256>>>(ascale);
    attn_av_kernel     <<<dim3(HWv/128, NHv, Bv), 256, AV_SMEM>>>();

    // 4. x = img + Wo@qkv + bo  (mode 5: + fused LN stats)
    gemm_kernel<<<dim3(32,2,Bv), 256, GEMM_SMEM>>>(wh+WO_O, wl+WO_O, xqkv_h, xqkv_l,
        xbuf, nullptr, nullptr, bo, img, 5, 256);

    // 5. MLP: single-pass LN apply, W1+gelu, W2+resid -> out
    ln_apply_kernel<<<LNB,256>>>(xbuf, mlnw, mlnb, xa_h, xa_l);
    gemm_kernel<<<dim3(32,2,Bv), 256, GEMM_SMEM>>>(wh+W1_O, wl+W1_O, xa_h, xa_l,
        nullptr, xh_h, xh_l, b1, nullptr, 1, 256);
    gemm_kernel<<<dim3(32,2,Bv), 256, GEMM_SMEM>>>(wh+W2_O, wl+W2_O, xh_h, xh_l,
        (float*)d_out, nullptr, nullptr, b2, xbuf, 2, 256);
}

// round 16
// speedup vs baseline: 2.1628x; 1.0436x over previous
#include <cuda_runtime.h>
#include <cuda_bf16.h>
#include <math.h>
#include <stdint.h>

#define Bv 8
#define Cv 256
#define HWv 4096
#define NHv 4
#define HDv 64

typedef __nv_bfloat16 bf16;

// ---------------- scratch (device globals; no allocations) ----------------
__device__ bf16 g_xa_h [Bv*HWv*Cv];
__device__ bf16 g_xa_l [Bv*HWv*Cv];
__device__ bf16 g_xkv_h[2*Bv*HWv*Cv];
__device__ bf16 g_xkv_l[2*Bv*HWv*Cv];
__device__ bf16 g_xqkv_h[Bv*HWv*Cv];
__device__ bf16 g_xqkv_l[Bv*HWv*Cv];
__device__ bf16 g_xh_h [Bv*HWv*Cv];
__device__ bf16 g_xh_l [Bv*HWv*Cv];
__device__ bf16 g_w_h[393216];
__device__ bf16 g_w_l[393216];
__device__ bf16 g_qb_h[Bv*Cv*HWv];         // q K-major [b][c][hw]
__device__ bf16 g_qb_l[Bv*Cv*HWv];
__device__ bf16 g_kb_h[2*Bv*Cv*HWv];       // k K-major [sb][c][hw]
__device__ bf16 g_kb_l[2*Bv*Cv*HWv];
__device__ bf16 g_vt_h[2*Bv*HWv*Cv];       // v transposed [sb][hw][c]
__device__ bf16 g_vt_l[2*Bv*HWv*Cv];
__device__ bf16 g_ph[2*Bv*NHv*HDv*HDv];
__device__ bf16 g_pl[2*Bv*NHv*HDv*HDv];
__device__ float g_x  [Bv*Cv*HWv];
__device__ float g_qinv[Bv*Cv];            // raw squared-sum accum
__device__ float g_kinv[2*Bv*Cv];
__device__ float g_lnsum[Bv*HWv];          // mlp-LN fused stats
__device__ float g_lnsq [Bv*HWv];
__device__ float g_spart[4*2*Bv*NHv*HDv*HDv];   // 4 splits

// ---------------- helpers ----------------
__device__ __forceinline__ uint32_t smem_to_u32(const void* p){
    uint32_t a;
    asm("{ .reg .u64 t; cvta.to.shared.u64 t, %1; cvt.u32.u64 %0, t; }" : "=r"(a) : "l"(p));
    return a;
}
__device__ __forceinline__ void ldmatrix_x4(uint32_t* r, uint32_t addr){
    asm volatile("ldmatrix.sync.aligned.m8n8.x4.shared.b16 {%0,%1,%2,%3}, [%4];"
        : "=r"(r[0]), "=r"(r[1]), "=r"(r[2]), "=r"(r[3]) : "r"(addr));
}
__device__ __forceinline__ void mma_bf16(float* d, const uint32_t* a, uint32_t b0, uint32_t b1){
    asm volatile("mma.sync.aligned.m16n8k16.row.col.f32.bf16.bf16.f32 "
        "{%0,%1,%2,%3}, {%4,%5,%6,%7}, {%8,%9}, {%0,%1,%2,%3};"
        : "+f"(d[0]), "+f"(d[1]), "+f"(d[2]), "+f"(d[3])
        : "r"(a[0]), "r"(a[1]), "r"(a[2]), "r"(a[3]), "r"(b0), "r"(b1));
}
__device__ __forceinline__ void cp_async16(uint32_t dst, const void* src){
    asm volatile("cp.async.cg.shared.global [%0], [%1], 16;" :: "r"(dst), "l"(src));
}
#define CP_COMMIT() asm volatile("cp.async.commit_group;" ::: "memory")
#define CP_WAIT(n)  asm volatile("cp.async.wait_group %0;" :: "n"(n) : "memory")

__device__ __forceinline__ float gelu_f(float v){
    float c = v + 0.044715f*v*v*v;
    float t = tanhf(0.7978845608028654f * c);
    return 0.5f*v*(1.f+t);
}
__device__ __forceinline__ void split_bf16(float v, bf16& h, bf16& l){
    h = __float2bfloat16(v);
    l = __float2bfloat16(v - __bfloat162float(h));
}

// ---------------- all-5 weight conversions + accumulator zeroing, one launch -----
__global__ void wconv5_kernel(const float* __restrict__ w0, const float* __restrict__ w1,
                              const float* __restrict__ w2, const float* __restrict__ w3,
                              const float* __restrict__ w4,
                              bf16* __restrict__ h, bf16* __restrict__ l){
    int i = blockIdx.x*256 + threadIdx.x;          // 0..393215
    const float* src; int j;
    if (i < 65536)       { src = w0; j = i; }
    else if (i < 196608) { src = w1; j = i - 65536; }
    else if (i < 262144) { src = w2; j = i - 196608; }
    else if (i < 327680) { src = w3; j = i - 262144; }
    else                 { src = w4; j = i - 327680; }
    bf16 hh, ll; split_bf16(src[j], hh, ll);
    h[i] = hh; l[i] = ll;
    // fold the accumulator zero-fills into this launch
    if (i < 4096){ if (i < 2048) g_qinv[i] = 0.f; g_kinv[i] = 0.f; }
    if (i < Bv*HWv){ g_lnsum[i] = 0.f; g_lnsq[i] = 0.f; }
}

// ---------------- merged LayerNorm (3 input tensors) -> XT bf16 hi/lo ------------
__global__ __launch_bounds__(256) void ln3_kernel(
        const float* __restrict__ img, const float* __restrict__ aux0,
        const float* __restrict__ aux1,
        const float* __restrict__ qw, const float* __restrict__ qb,
        const float* __restrict__ kw, const float* __restrict__ kb,
        bf16* __restrict__ xa_h, bf16* __restrict__ xa_l,
        bf16* __restrict__ xkv_h, bf16* __restrict__ xkv_l)
{
    int which = blockIdx.y;
    const float* x = (which == 0) ? img : (which == 1) ? aux0 : aux1;
    const float* w = (which == 0) ? qw : kw;
    const float* bias = (which == 0) ? qb : kb;
    bf16* oh = (which == 0) ? xa_h : xkv_h + (size_t)(which-1)*Bv*HWv*Cv;
    bf16* ol = (which == 0) ? xa_l : xkv_l + (size_t)(which-1)*Bv*HWv*Cv;

    int idx = blockIdx.x*blockDim.x + threadIdx.x;
    int b = idx / HWv, hw = idx % HWv;
    const float* xb = x + (size_t)b*Cv*HWv + hw;
    float s = 0.f, s2 = 0.f;
    #pragma unroll 8
    for (int c = 0; c < Cv; c++){ float v = xb[(size_t)c*HWv]; s += v; s2 += v*v; }
    float m   = s * (1.f/Cv);
    float var = s2 * (1.f/Cv) - m*m;
    float inv = rsqrtf(var + 1e-5f);
    size_t base = ((size_t)b*HWv + hw) * Cv;
    for (int c8 = 0; c8 < Cv/8; c8++){
        uint4 hp, lp;
        bf16* hh = (bf16*)&hp; bf16* ll = (bf16*)&lp;
        #pragma unroll
        for (int i = 0; i < 8; i++){
            int c = c8*8 + i;
            float v = (xb[(size_t)c*HWv] - m) * inv * w[c] + bias[c];
            split_bf16(v, hh[i], ll[i]);
        }
        *(uint4*)&oh[base + c8*8] = hp;
        *(uint4*)&ol[base + c8*8] = lp;
    }
}

// ---------------- single-pass LN apply using fused stats (mlp LN) ----------------
__global__ __launch_bounds__(256) void ln_apply_kernel(const float* __restrict__ x,
        const float* __restrict__ w, const float* __restrict__ bias,
        bf16* __restrict__ oh, bf16* __restrict__ ol)
{
    int idx = blockIdx.x*blockDim.x + threadIdx.x;
    int b = idx / HWv, hw = idx % HWv;
    float s  = g_lnsum[idx];
    float s2 = g_lnsq[idx];
    float m   = s * (1.f/Cv);
    float var = s2 * (1.f/Cv) - m*m;
    float inv = rsqrtf(var + 1e-5f);
    const float* xb = x + (size_t)b*Cv*HWv + hw;
    size_t base = ((size_t)b*HWv + hw) * Cv;
    for (int c8 = 0; c8 < Cv/8; c8++){
        uint4 hp, lp;
        bf16* hh = (bf16*)&hp; bf16* ll = (bf16*)&lp;
        #pragma unroll
        for (int i = 0; i < 8; i++){
            int c = c8*8 + i;
            float v = (xb[(size_t)c*HWv] - m) * inv * w[c] + bias[c];
            split_bf16(v, hh[i], ll[i]);
        }
        *(uint4*)&oh[base + c8*8] = hp;
        *(uint4*)&ol[base + c8*8] = lp;
    }
}

// ---------------- HMMA bf16x3 GEMM (R6-proven mainloop, occ 2) -------------------
// mode 1: oxh/oxl bf16 XT [b][hw][c], +bias, gelu
// mode 2: out fp32, +bias +resid
// mode 5: mode 2 + fused LN stats atomics into g_lnsum/g_lnsq
#define RS 72
#define OFF_AH 0
#define OFF_AL 18432
#define OFF_BH 36864
#define OFF_BL 55296
#define GEMM_SMEM 73728

__global__ __launch_bounds__(256,2) void gemm_kernel(
    const bf16* __restrict__ Ah, const bf16* __restrict__ Al,
    const bf16* __restrict__ Bh, const bf16* __restrict__ Bl,
    float* __restrict__ out, bf16* __restrict__ oxh, bf16* __restrict__ oxl,
    const float* __restrict__ bias, const float* __restrict__ resid,
    int mode, int Mrows)
{
    extern __shared__ char sm[];
    uint32_t smb = smem_to_u32(sm);
    int tid = threadIdx.x, lane = tid & 31, warp = tid >> 5;
    int warp_m = warp & 3, warp_n = warp >> 2;
    int n0 = blockIdx.x*128, m0 = blockIdx.y*128, b = blockIdx.z;
    const bf16* Bhb = Bh + (size_t)b*HWv*Cv;
    const bf16* Blb = Bl + (size_t)b*HWv*Cv;

    float d[2][8][4];
    #pragma unroll
    for (int i=0;i<2;i++)
        #pragma unroll
        for (int j=0;j<8;j++)
            #pragma unroll
            for (int k=0;k<4;k++) d[i][j][k] = 0.f;

    int a_row = (lane & 7) + ((lane >> 3) & 1) * 8;
    int a_kc  = (lane >> 4) * 8;
    int b_row = (lane & 7) + (lane >> 4) * 8;
    int b_kc  = ((lane >> 3) & 1) * 8;

    for (int kt = 0; kt < 4; kt++){
        int k0 = kt*64;
        #pragma unroll
        for (int it = 0; it < 4; it++){
            int lin = tid + it*256;
            int row = lin >> 3, kk = lin & 7;
            uint32_t so = row*(RS*2) + kk*16;
            size_t ga = (size_t)(m0+row)*Cv + k0 + kk*8;
            size_t gb = (size_t)(n0+row)*Cv + k0 + kk*8;
            *(uint4*)(sm+OFF_AH+so) = *(const uint4*)(Ah +ga);
            *(uint4*)(sm+OFF_AL+so) = *(const uint4*)(Al +ga);
            *(uint4*)(sm+OFF_BH+so) = *(const uint4*)(Bhb+gb);
            *(uint4*)(sm+OFF_BL+so) = *(const uint4*)(Blb+gb);
        }
        __syncthreads();
        #pragma unroll
        for (int k16 = 0; k16 < 4; k16++){
            uint32_t ah[2][4], al[2][4];
            #pragma unroll
            for (int fm = 0; fm < 2; fm++){
                int arow = warp_m*32 + fm*16 + a_row;
                uint32_t aaddr = smb + OFF_AH + arow*(RS*2) + (k16*16 + a_kc)*2;
                ldmatrix_x4(ah[fm], aaddr);
                ldmatrix_x4(al[fm], aaddr + (OFF_AL-OFF_AH));
            }
            #pragma unroll
            for (int half = 0; half < 2; half++){
                uint32_t bh[2][4], bl[2][4];
                #pragma unroll
                for (int p = 0; p < 2; p++){
                    int nrow = warp_n*64 + half*32 + p*16 + b_row;
                    uint32_t baddr = smb + OFF_BH + nrow*(RS*2) + (k16*16 + b_kc)*2;
                    ldmatrix_x4(bh[p], baddr);
                    ldmatrix_x4(bl[p], baddr + (OFF_BL-OFF_BH));
                }
                #pragma unroll
                for (int fm = 0; fm < 2; fm++)
                    #pragma unroll
                    for (int j = 0; j < 4; j++){
                        float* dd = d[fm][half*4+j];
                        uint32_t* fh = &bh[j>>1][(j&1)*2];
                        uint32_t* fl = &bl[j>>1][(j&1)*2];
                        mma_bf16(dd, ah[fm], fh[0], fh[1]);
                        mma_bf16(dd, ah[fm], fl[0], fl[1]);
                        mma_bf16(dd, al[fm], fh[0], fh[1]);
                    }
            }
        }
        __syncthreads();
    }

    float* stage = (float*)sm;            // [128][132]
    #pragma unroll
    for (int fm = 0; fm < 2; fm++)
        #pragma unroll
        for (int fn = 0; fn < 8; fn++){
            int row = warp_m*32 + fm*16 + (lane>>2);
            int col = warp_n*64 + fn*8 + 2*(lane&3);
            *(float2*)&stage[row*132+col]     = make_float2(d[fm][fn][0], d[fm][fn][1]);
            *(float2*)&stage[(row+8)*132+col] = make_float2(d[fm][fn][2], d[fm][fn][3]);
        }
    __syncthreads();

    if (mode == 2 || mode == 5){
        int col = tid & 127, mr0 = tid >> 7;
        float ls = 0.f, ls2 = 0.f;
        #pragma unroll 8
        for (int it = 0; it < 64; it++){
            int m = it*2 + mr0;
            float v = stage[m*132 + col];
            size_t o = ((size_t)b*Mrows + m0 + m)*HWv + n0 + col;
            v += bias[m0+m] + resid[o];
            out[o] = v;
            ls += v; ls2 += v*v;
        }
        if (mode == 5){
            atomicAdd(&g_lnsum[(size_t)b*HWv + n0 + col], ls);
            atomicAdd(&g_lnsq [(size_t)b*HWv + n0 + col], ls2);
        }
    } else {  // mode 1
        int n = tid >> 1;
        int mh = (tid & 1) * 64;
        size_t ro = ((size_t)b*HWv + n0 + n)*Cv + m0 + mh;
        #pragma unroll
        for (int c8 = 0; c8 < 8; c8++){
            uint4 hp, lp;
            bf16* hh = (bf16*)&hp; bf16* ll = (bf16*)&lp;
            #pragma unroll
            for (int i = 0; i < 8; i++){
                int m = mh + c8*8 + i;
                float v = gelu_f(stage[m*132 + n] + bias[m0 + m]);
                split_bf16(v, hh[i], ll[i]);
            }
            *(uint4*)&oxh[ro + c8*8] = hp;
            *(uint4*)&oxl[ro + c8*8] = lp;
        }
    }
}

// ---------------- merged Wq+Wkv projection GEMM (flat grid, 2560 CTAs) -----------
__global__ __launch_bounds__(256,2) void gemm_qkv_kernel()
{
    extern __shared__ char sm[];
    uint32_t smb = smem_to_u32(sm);
    int tid = threadIdx.x, lane = tid & 31, warp = tid >> 5;
    int warp_m = warp & 3, warp_n = warp >> 2;

    const bf16 *Ah, *Al, *Bh, *Bl;
    int m0, n0, b, job;                      // job 0 = Wq, 1 = Wkv
    {
        int cta = blockIdx.x;
        if (cta < 512){
            job = 0; n0 = (cta & 31) << 7; m0 = ((cta >> 5) & 1) << 7; b = cta >> 6;
            Ah = g_w_h;          Al = g_w_l;
            Bh = g_xa_h + (size_t)b*HWv*Cv;  Bl = g_xa_l + (size_t)b*HWv*Cv;
        } else {
            int c2 = cta - 512;
            job = 1; n0 = (c2 & 31) << 7; m0 = ((c2 >> 5) & 3) << 7; b = c2 >> 7;
            Ah = g_w_h + 65536;  Al = g_w_l + 65536;
            Bh = g_xkv_h + (size_t)b*HWv*Cv; Bl = g_xkv_l + (size_t)b*HWv*Cv;
        }
    }

    float d[2][8][4];
    #pragma unroll
    for (int i=0;i<2;i++)
        #pragma unroll
        for (int j=0;j<8;j++)
            #pragma unroll
            for (int k=0;k<4;k++) d[i][j][k] = 0.f;

    int a_row = (lane & 7) + ((lane >> 3) & 1) * 8;
    int a_kc  = (lane >> 4) * 8;
    int b_row = (lane & 7) + (lane >> 4) * 8;
    int b_kc  = ((lane >> 3) & 1) * 8;

    for (int kt = 0; kt < 4; kt++){
        int k0 = kt*64;
        #pragma unroll
        for (int it = 0; it < 4; it++){
            int lin = tid + it*256;
            int row = lin >> 3, kk = lin & 7;
            uint32_t so = row*(RS*2) + kk*16;
            size_t ga = (size_t)(m0+row)*Cv + k0 + kk*8;
            size_t gb = (size_t)(n0+row)*Cv + k0 + kk*8;
            *(uint4*)(sm+OFF_AH+so) = *(const uint4*)(Ah+ga);
            *(uint4*)(sm+OFF_AL+so) = *(const uint4*)(Al+ga);
            *(uint4*)(sm+OFF_BH+so) = *(const uint4*)(Bh+gb);
            *(uint4*)(sm+OFF_BL+so) = *(const uint4*)(Bl+gb);
        }
        __syncthreads();
        #pragma unroll
        for (int k16 = 0; k16 < 4; k16++){
            uint32_t ah[2][4], al[2][4];
            #pragma unroll
            for (int fm = 0; fm < 2; fm++){
                int arow = warp_m*32 + fm*16 + a_row;
                uint32_t aaddr = smb + OFF_AH + arow*(RS*2) + (k16*16 + a_kc)*2;
                ldmatrix_x4(ah[fm], aaddr);
                ldmatrix_x4(al[fm], aaddr + (OFF_AL-OFF_AH));
            }
            #pragma unroll
            for (int half = 0; half < 2; half++){
                uint32_t bh[2][4], bl[2][4];
                #pragma unroll
                for (int p = 0; p < 2; p++){
                    int nrow = warp_n*64 + half*32 + p*16 + b_row;
                    uint32_t baddr = smb + OFF_BH + nrow*(RS*2) + (k16*16 + b_kc)*2;
                    ldmatrix_x4(bh[p], baddr);
                    ldmatrix_x4(bl[p], baddr + (OFF_BL-OFF_BH));
                }
                #pragma unroll
                for (int fm = 0; fm < 2; fm++)
                    #pragma unroll
                    for (int j = 0; j < 4; j++){
                        float* dd = d[fm][half*4+j];
                        uint32_t* fh = &bh[j>>1][(j&1)*2];
                        uint32_t* fl = &bl[j>>1][(j&1)*2];
                        mma_bf16(dd, ah[fm], fh[0], fh[1]);
                        mma_bf16(dd, ah[fm], fl[0], fl[1]);
                        mma_bf16(dd, al[fm], fh[0], fh[1]);
                    }
            }
        }
        __syncthreads();
    }

    float* stage = (float*)sm;
    #pragma unroll
    for (int fm = 0; fm < 2; fm++)
        #pragma unroll
        for (int fn = 0; fn < 8; fn++){
            int row = warp_m*32 + fm*16 + (lane>>2);
            int col = warp_n*64 + fn*8 + 2*(lane&3);
            *(float2*)&stage[row*132+col]     = make_float2(d[fm][fn][0], d[fm][fn][1]);
            *(float2*)&stage[(row+8)*132+col] = make_float2(d[fm][fn][2], d[fm][fn][3]);
        }
    __syncthreads();

    if (job == 0 || m0 < 256){
        // K-major bf16 hi/lo out + fused squared-row-sum atomics (q or k)
        bf16* oh  = (job == 0) ? g_qb_h : g_kb_h;
        bf16* ol  = (job == 0) ? g_qb_l : g_kb_l;
        float* nrm = (job == 0) ? g_qinv : g_kinv;
        int n2 = (tid & 63)*2, mr = tid >> 6;
        #pragma unroll 8
        for (int it = 0; it < 32; it++){
            int m = it*4 + mr;
            float v0 = stage[m*132 + n2], v1 = stage[m*132 + n2 + 1];
            bf16 hb[2], lb[2];
            split_bf16(v0, hb[0], lb[0]);
            split_bf16(v1, hb[1], lb[1]);
            size_t o = ((size_t)b*Cv + m0 + m)*HWv + n0 + n2;
            *(uint32_t*)&oh[o] = *(uint32_t*)hb;
            *(uint32_t*)&ol[o] = *(uint32_t*)lb;
            float p = v0*v0 + v1*v1;
            #pragma unroll
            for (int off = 16; off > 0; off >>= 1)
                p += __shfl_xor_sync(0xffffffffu, p, off);
            if (lane == 0) atomicAdd(&nrm[b*Cv + m0 + m], p);
        }
    } else {
        // v -> XT bf16 hi/lo [sb][hw][c]
        int n = tid >> 1;
        int mh = (tid & 1) * 64;
        size_t ro = ((size_t)b*HWv + n0 + n)*Cv + (m0 - 256) + mh;
        #pragma unroll
        for (int c8 = 0; c8 < 8; c8++){
            uint4 hp, lp;
            bf16* hh = (bf16*)&hp; bf16* ll = (bf16*)&lp;
            #pragma unroll
            for (int i = 0; i < 8; i++){
                int m = mh + c8*8 + i;
                split_bf16(stage[m*132 + n], hh[i], ll[i]);
            }
            *(uint4*)&g_vt_h[ro + c8*8] = hp;
            *(uint4*)&g_vt_l[ro + c8*8] = lp;
        }
    }
}

// ---------------- HMMA split-K S = q @ k^T  (4 splits, cp.async 2-stage) ---------
#define SSTG 36864
#define ATTN_S_SMEM (2*SSTG)
__global__ __launch_bounds__(256) void attn_s_kernel()
{
    extern __shared__ char sm[];
    uint32_t smb = smem_to_u32(sm);
    int tid = threadIdx.x, lane = tid & 31, warp = tid >> 5;
    int warp_m = warp & 3, warp_n = warp >> 2;
    int split = blockIdx.x;                      // 0..3
    int sn = blockIdx.y, s = sn >> 2, n = sn & 3;
    int b = blockIdx.z;

    const bf16* srcs[4];
    srcs[0] = g_qb_h + ((size_t)b*Cv + n*HDv) * HWv;
    srcs[1] = g_qb_l + ((size_t)b*Cv + n*HDv) * HWv;
    srcs[2] = g_kb_h + ((size_t)(s*Bv + b)*Cv + n*HDv) * HWv;
    srcs[3] = g_kb_l + ((size_t)(s*Bv + b)*Cv + n*HDv) * HWv;

    int a_row = (lane & 7) + ((lane >> 3) & 1) * 8;
    int a_kc  = (lane >> 4) * 8;
    int b_row = (lane & 7) + (lane >> 4) * 8;
    int b_kc  = ((lane >> 3) & 1) * 8;

    float d[4][4];
    #pragma unroll
    for (int i=0;i<4;i++)
        #pragma unroll
        for (int j=0;j<4;j++) d[i][j] = 0.f;

    // issue one 64-wide hw chunk into stage (kc&1): identical indexing to R14 loads
    #define S_ISSUE(kc) do {                                                      \
        int _hwb = split*1024 + (kc)*64;                                          \
        uint32_t _sb = smb + ((kc)&1)*SSTG;                                       \
        _Pragma("unroll")                                                         \
        for (int _arr = 0; _arr < 4; _arr++)                                      \
            _Pragma("unroll")                                                     \
            for (int _hf = 0; _hf < 2; _hf++){                                    \
                int _rem = tid + _hf*256;                                         \
                int _row = _rem >> 3, _c8 = _rem & 7;                             \
                cp_async16(_sb + _arr*9216 + _row*144 + _c8*16,                   \
                           srcs[_arr] + (size_t)_row*HWv + _hwb + _c8*8);         \
            }                                                                     \
        CP_COMMIT();                                                              \
    } while(0)

    S_ISSUE(0);
    S_ISSUE(1);

    for (int kc = 0; kc < 16; kc++){
        if (kc < 15) { CP_WAIT(1); } else { CP_WAIT(0); }
        __syncthreads();
        uint32_t sb = smb + (kc&1)*SSTG;
        #pragma unroll
        for (int k16 = 0; k16 < 4; k16++){
            uint32_t ah[4], al[4];
            int arow = warp_m*16 + a_row;
            uint32_t abase = sb + arow*144 + (k16*16 + a_kc)*2;
            ldmatrix_x4(ah, abase);
            ldmatrix_x4(al, abase + 9216);
            #pragma unroll
            for (int p = 0; p < 2; p++){
                uint32_t bh[4], bl[4];
                int nrow = warp_n*32 + p*16 + b_row;
                uint32_t bbase = sb + 18432 + nrow*144 + (k16*16 + b_kc)*2;
                ldmatrix_x4(bh, bbase);
                ldmatrix_x4(bl, bbase + 9216);
                #pragma unroll
                for (int j = 0; j < 2; j++){
                    float* dd = d[p*2+j];
                    mma_bf16(dd, ah, bh[j*2], bh[j*2+1]);
                    mma_bf16(dd, ah, bl[j*2], bl[j*2+1]);
                    mma_bf16(dd, al, bh[j*2], bh[j*2+1]);
                }
            }
        }
        __syncthreads();
        if (kc + 2 < 16) S_ISSUE(kc + 2);
    }
    float* op = g_spart + ((((size_t)split*2 + s)*Bv + b)*NHv + n) * 4096;
    int r = warp_m*16 + (lane>>2);
    #pragma unroll
    for (int fn = 0; fn < 4; fn++){
        int col = warp_n*32 + fn*8 + 2*(lane&3);
        *(float2*)&op[r*64+col]     = make_float2(d[fn][0], d[fn][1]);
        *(float2*)&op[(r+8)*64+col] = make_float2(d[fn][2], d[fn][3]);
    }
}

// ---------------- sum partials, inv-norms inline, softmax, gate -> bf16 P --------
__global__ __launch_bounds__(256) void attn_softmax_kernel(const float* __restrict__ attn_scale)
{
    int n = blockIdx.x, b = blockIdx.y, s = blockIdx.z;
    __shared__ float S[64][65];
    __shared__ float qi[64], ki[64], rfac[64];
    int tid = threadIdx.x;
    if (tid < 64){
        qi[tid] = 1.f / fmaxf(sqrtf(g_qinv[b*Cv + n*HDv + tid]), 1e-12f);
        ki[tid] = 1.f / fmaxf(sqrtf(g_kinv[(s*Bv + b)*Cv + n*HDv + tid]), 1e-12f);
    }
    __syncthreads();
    size_t moff = (((size_t)s*Bv + b)*NHv + n) * 4096;
    for (int idx = tid; idx < 4096; idx += 256){
        int c = idx >> 6, dd = idx & 63;
        float a = 0.f;
        #pragma unroll
        for (int sp = 0; sp < 4; sp++)
            a += g_spart[((((size_t)sp*2 + s)*Bv + b)*NHv + n)*4096 + idx];
        S[c][dd] = a * qi[c] * ki[dd];
    }
    __syncthreads();
    if (tid < 64){
        int c = tid;
        float g = 1.f / (1.f + expf(-attn_scale[n]));
        float factor = (s == 0) ? g : (1.f - g);
        float mx = -1e30f;
        for (int dd = 0; dd < 64; dd++) mx = fmaxf(mx, S[c][dd]);
        float sum = 0.f;
        for (int dd = 0; dd < 64; dd++){ float e = expf(S[c][dd] - mx); S[c][dd] = e; sum += e; }
        rfac[c] = factor / sum;
    }
    __syncthreads();
    for (int idx = tid; idx < 4096; idx += 256){
        int c = idx >> 6, dd = idx & 63;
        bf16 h, l;
        split_bf16(S[c][dd] * rfac[c], h, l);
        g_ph[moff + idx] = h;
        g_pl[moff + idx] = l;
    }
}

// ---------------- HMMA qkv = Ptex@Vt + Pdep@Vd -> XT bf16 hi/lo ------------------
#define AVO_V 36864
#define AV_SMEM (36864 + 4*18432)
__global__ __launch_bounds__(256) void attn_av_kernel()
{
    extern __shared__ char sm[];
    uint32_t smb = smem_to_u32(sm);
    int tid = threadIdx.x, lane = tid & 31, warp = tid >> 5;
    int warp_m = warp & 3, warp_n = warp >> 2;
    int hw0 = blockIdx.x * 128;
    int n = blockIdx.y, b = blockIdx.z;

    size_t offT = (((size_t)0*Bv + b)*NHv + n) * 4096;
    size_t offD = (((size_t)1*Bv + b)*NHv + n) * 4096;
    const bf16* psrc[4] = {g_ph + offT, g_pl + offT, g_ph + offD, g_pl + offD};
    const bf16* vsrc[4];
    vsrc[0] = g_vt_h + (size_t)b*HWv*Cv;
    vsrc[1] = g_vt_l + (size_t)b*HWv*Cv;
    vsrc[2] = g_vt_h + (size_t)(Bv + b)*HWv*Cv;
    vsrc[3] = g_vt_l + (size_t)(Bv + b)*HWv*Cv;

    #pragma unroll
    for (int arr = 0; arr < 4; arr++)
        #pragma unroll
        for (int hf = 0; hf < 2; hf++){
            int rem = tid + hf*256;
            int row = rem >> 3, c8 = rem & 7;
            *(uint4*)(sm + arr*9216 + row*144 + c8*16) =
                *(const uint4*)(psrc[arr] + row*64 + c8*8);
        }
    #pragma unroll
    for (int arr = 0; arr < 4; arr++)
        #pragma unroll
        for (int hf = 0; hf < 4; hf++){
            int rem = tid + hf*256;
            int row = rem >> 3, c8 = rem & 7;
            *(uint4*)(sm + AVO_V + arr*18432 + row*144 + c8*16) =
                *(const uint4*)(vsrc[arr] + (size_t)(hw0+row)*Cv + n*HDv + c8*8);
        }
    __syncthreads();

    int a_row = (lane & 7) + ((lane >> 3) & 1) * 8;
    int a_kc  = (lane >> 4) * 8;
    int b_row = (lane & 7) + (lane >> 4) * 8;
    int b_kc  = ((lane >> 3) & 1) * 8;

    float d[8][4];
    #pragma unroll
    for (int i=0;i<8;i++)
        #pragma unroll
        for (int j=0;j<4;j++) d[i][j] = 0.f;

    #pragma unroll
    for (int k16 = 0; k16 < 4; k16++){
        uint32_t ath[4], atl[4], adh[4], adl[4];
        int arow = warp_m*16 + a_row;
        uint32_t abase = smb + arow*144 + (k16*16 + a_kc)*2;
        ldmatrix_x4(ath, abase);
        ldmatrix_x4(atl, abase + 9216);
        ldmatrix_x4(adh, abase + 18432);
        ldmatrix_x4(adl, abase + 27648);
        #pragma unroll
        for (int p = 0; p < 4; p++){
            uint32_t bth[4], btl[4], bdh[4], bdl[4];
            int nrow = warp_n*64 + p*16 + b_row;
            uint32_t bbase = smb + AVO_V + nrow*144 + (k16*16 + b_kc)*2;
            ldmatrix_x4(bth, bbase);
            ldmatrix_x4(btl, bbase + 18432);
            ldmatrix_x4(bdh, bbase + 36864);
            ldmatrix_x4(bdl, bbase + 55296);
            #pragma unroll
            for (int j = 0; j < 2; j++){
                float* dd = d[p*2+j];
                mma_bf16(dd, ath, bth[j*2], bth[j*2+1]);
                mma_bf16(dd, ath, btl[j*2], btl[j*2+1]);
                mma_bf16(dd, atl, bth[j*2], bth[j*2+1]);
                mma_bf16(dd, adh, bdh[j*2], bdh[j*2+1]);
                mma_bf16(dd, adh, bdl[j*2], bdl[j*2+1]);
                mma_bf16(dd, adl, bdh[j*2], bdh[j*2+1]);
            }
        }
    }
    __syncthreads();
    float* stage = (float*)sm;
    int r = warp_m*16 + (lane>>2);
    #pragma unroll
    for (int fn = 0; fn < 8; fn++){
        int col = warp_n*64 + fn*8 + 2*(lane&3);
        *(float2*)&stage[r*132+col]     = make_float2(d[fn][0], d[fn][1]);
        *(float2*)&stage[(r+8)*132+col] = make_float2(d[fn][2], d[fn][3]);
    }
    __syncthreads();
    int hw_l = tid >> 1, c0 = (tid & 1) * 32;
    #pragma unroll
    for (int q4 = 0; q4 < 4; q4++){
        uint4 hp, lp;
        bf16* hh = (bf16*)&hp; bf16* ll = (bf16*)&lp;
        #pragma unroll
        for (int i = 0; i < 8; i++){
            float v = stage[(c0 + q4*8 + i)*132 + hw_l];
            split_bf16(v, hh[i], ll[i]);
        }
        size_t ro = ((size_t)b*HWv + hw0 + hw_l)*Cv + n*HDv + c0 + q4*8;
        *(uint4*)&g_xqkv_h[ro] = hp;
        *(uint4*)&g_xqkv_l[ro] = lp;
    }
}

// ---------------- host launcher ----------------
extern "C" void kernel_launch(void* const* d_in, const int* in_sizes, int n_in,
                              void* d_out, int out_size)
{
    const float* img    = (const float*)d_in[0];
    const float* aux0   = (const float*)d_in[1];
    const float* aux1   = (const float*)d_in[2];
    const float* qlnw   = (const float*)d_in[3];
    const float* qlnb   = (const float*)d_in[4];
    const float* kvlnw  = (const float*)d_in[5];
    const float* kvlnb  = (const float*)d_in[6];
    const float* Wq     = (const float*)d_in[7];
    const float* Wkv    = (const float*)d_in[8];
    const float* Wo     = (const float*)d_in[9];
    const float* bo     = (const float*)d_in[10];
    const float* ascale = (const float*)d_in[11];
    const float* mlnw   = (const float*)d_in[12];
    const float* mlnb   = (const float*)d_in[13];
    const float* W1     = (const float*)d_in[14];
    const float* b1     = (const float*)d_in[15];
    const float* W2     = (const float*)d_in[16];
    const float* b2     = (const float*)d_in[17];

    bf16 *xa_h,*xa_l,*xkv_h,*xkv_l,*xqkv_h,*xqkv_l,*xh_h,*xh_l,*wh,*wl;
    float *xbuf;
    cudaGetSymbolAddress((void**)&xa_h,  g_xa_h);
    cudaGetSymbolAddress((void**)&xa_l,  g_xa_l);
    cudaGetSymbolAddress((void**)&xkv_h, g_xkv_h);
    cudaGetSymbolAddress((void**)&xkv_l, g_xkv_l);
    cudaGetSymbolAddress((void**)&xqkv_h,g_xqkv_h);
    cudaGetSymbolAddress((void**)&xqkv_l,g_xqkv_l);
    cudaGetSymbolAddress((void**)&xh_h,  g_xh_h);
    cudaGetSymbolAddress((void**)&xh_l,  g_xh_l);
    cudaGetSymbolAddress((void**)&wh,    g_w_h);
    cudaGetSymbolAddress((void**)&wl,    g_w_l);
    cudaGetSymbolAddress((void**)&xbuf,  g_x);

    cudaFuncSetAttribute(gemm_kernel,
                         cudaFuncAttributeMaxDynamicSharedMemorySize, GEMM_SMEM);
    cudaFuncSetAttribute(gemm_qkv_kernel,
                         cudaFuncAttributeMaxDynamicSharedMemorySize, GEMM_SMEM);
    cudaFuncSetAttribute(attn_s_kernel,
                         cudaFuncAttributeMaxDynamicSharedMemorySize, ATTN_S_SMEM);
    cudaFuncSetAttribute(attn_av_kernel,
                         cudaFuncAttributeMaxDynamicSharedMemorySize, AV_SMEM);

    const int WO_O = 196608, W1_O = 262144, W2_O = 327680;

    // 0. all weight conversions + accumulator zeroing in one launch
    wconv5_kernel<<<1536,256>>>(Wq, Wkv, Wo, W1, W2, wh, wl);

    const int LNB = (Bv*HWv)/256;   // 128

    // 1. All three input LayerNorms in one launch
    ln3_kernel<<<dim3(LNB,3),256>>>(img, aux0, aux1, qlnw, qlnb, kvlnw, kvlnb,
                                    xa_h, xa_l, xkv_h, xkv_l);

    // 2. Merged Wq + Wkv projections (flat grid) with fused sq-sum atomics
    gemm_qkv_kernel<<<2560, 256, GEMM_SMEM>>>();

    // 3. Attention (HMMA; 4-way split-K S with cp.async pipeline)
    attn_s_kernel      <<<dim3(4, 2*NHv, Bv), 256, ATTN_S_SMEM>>>();
    attn_softmax_kernel<<<dim3(NHv, Bv, 2),   256>>>(ascale);
    attn_av_kernel     <<<dim3(HWv/128, NHv, Bv), 256, AV_SMEM>>>();

    // 4. x = img + Wo@qkv + bo  (mode 5: + fused LN stats)
    gemm_kernel<<<dim3(32,2,Bv), 256, GEMM_SMEM>>>(wh+WO_O, wl+WO_O, xqkv_h, xqkv_l,
        xbuf, nullptr, nullptr, bo, img, 5, 256);

    // 5. MLP: single-pass LN apply, W1+gelu, W2+resid -> out
    ln_apply_kernel<<<LNB,256>>>(xbuf, mlnw, mlnb, xa_h, xa_l);
    gemm_kernel<<<dim3(32,2,Bv), 256, GEMM_SMEM>>>(wh+W1_O, wl+W1_O, xa_h, xa_l,
        nullptr, xh_h, xh_l, b1, nullptr, 1, 256);
    gemm_kernel<<<dim3(32,2,Bv), 256, GEMM_SMEM>>>(wh+W2_O, wl+W2_O, xh_h, xh_l,
        (float*)d_out, nullptr, nullptr, b2, xbuf, 2, 256);
}